// round 1
// baseline (speedup 1.0000x reference)
#include <cuda_runtime.h>
#include <math.h>

#define BATCH 2
#define SQ    2048
#define DIM   1024
#define NH    16
#define HD    64
#define ROWS  (BATCH * SQ)   // 4096
#define EPSV  1e-5f

// ---------------------------------------------------------------------------
// Scratch (device globals — allocation rules forbid cudaMalloc)
// ---------------------------------------------------------------------------
__device__ float g_xn[ROWS * DIM];        // 16 MB   prenormed x
__device__ float g_qkv[ROWS * 3 * DIM];   // 48 MB   qkv (q/k rms-normed in place)
__device__ float g_gate[ROWS * NH];       //         sigmoid(gate)
__device__ float g_att[ROWS * DIM];       // 16 MB   gated attention out, [b,s,h,d]

// ---------------------------------------------------------------------------
// 1) prenorm RMS: one block per row of 1024
// ---------------------------------------------------------------------------
__global__ __launch_bounds__(256) void prenorm_kernel(
    const float* __restrict__ x, const float* __restrict__ w, float* __restrict__ xn)
{
    int row = blockIdx.x;
    const float* xr = x + (size_t)row * DIM;
    float ss = 0.f;
    #pragma unroll
    for (int i = threadIdx.x; i < DIM; i += 256) { float v = xr[i]; ss += v * v; }
    __shared__ float red[256];
    red[threadIdx.x] = ss;
    __syncthreads();
    for (int s = 128; s > 0; s >>= 1) {
        if (threadIdx.x < s) red[threadIdx.x] += red[threadIdx.x + s];
        __syncthreads();
    }
    float scale = rsqrtf(red[0] * (1.0f / DIM) + EPSV);
    float* xo = xn + (size_t)row * DIM;
    #pragma unroll
    for (int i = threadIdx.x; i < DIM; i += 256) xo[i] = xr[i] * scale * w[i];
}

// ---------------------------------------------------------------------------
// 2) NT SGEMM: C[M,N] = A[M,K] * W[N,K]^T (+ optional residual R[M,N])
//    128x128 block tile, BK=8, 256 threads, 8x8 per thread
// ---------------------------------------------------------------------------
__global__ __launch_bounds__(256) void sgemm_nt(
    const float* __restrict__ A, const float* __restrict__ W,
    const float* __restrict__ R, float* __restrict__ C, int N, int K)
{
    __shared__ float As[8][128];
    __shared__ float Bs[8][128];
    int tid = threadIdx.x;
    int m0 = blockIdx.y * 128, n0 = blockIdx.x * 128;
    int lr = tid >> 1;            // 0..127 (tile row for loading)
    int lc = (tid & 1) * 4;       // 0 or 4 (k offset for loading)
    int ty = tid >> 4;            // 0..15
    int tx = tid & 15;            // 0..15

    float acc[8][8];
    #pragma unroll
    for (int i = 0; i < 8; i++)
        #pragma unroll
        for (int j = 0; j < 8; j++) acc[i][j] = 0.f;

    const float* aptr = A + (size_t)(m0 + lr) * K + lc;
    const float* bptr = W + (size_t)(n0 + lr) * K + lc;

    for (int k0 = 0; k0 < K; k0 += 8) {
        float4 av = *(const float4*)(aptr + k0);
        float4 bv = *(const float4*)(bptr + k0);
        As[lc + 0][lr] = av.x; As[lc + 1][lr] = av.y;
        As[lc + 2][lr] = av.z; As[lc + 3][lr] = av.w;
        Bs[lc + 0][lr] = bv.x; Bs[lc + 1][lr] = bv.y;
        Bs[lc + 2][lr] = bv.z; Bs[lc + 3][lr] = bv.w;
        __syncthreads();
        #pragma unroll
        for (int k = 0; k < 8; k++) {
            float a[8], b[8];
            *(float4*)(a)     = *(const float4*)&As[k][ty * 8];
            *(float4*)(a + 4) = *(const float4*)&As[k][ty * 8 + 4];
            *(float4*)(b)     = *(const float4*)&Bs[k][tx * 8];
            *(float4*)(b + 4) = *(const float4*)&Bs[k][tx * 8 + 4];
            #pragma unroll
            for (int i = 0; i < 8; i++)
                #pragma unroll
                for (int j = 0; j < 8; j++)
                    acc[i][j] = fmaf(a[i], b[j], acc[i][j]);
        }
        __syncthreads();
    }

    #pragma unroll
    for (int i = 0; i < 8; i++) {
        size_t row = (size_t)(m0 + ty * 8 + i);
        float* crow = C + row * N + n0 + tx * 8;
        #pragma unroll
        for (int j = 0; j < 8; j += 4) {
            float4 v = make_float4(acc[i][j], acc[i][j+1], acc[i][j+2], acc[i][j+3]);
            if (R) {
                float4 r = *(const float4*)(R + row * N + n0 + tx * 8 + j);
                v.x += r.x; v.y += r.y; v.z += r.z; v.w += r.w;
            }
            *(float4*)(crow + j) = v;
        }
    }
}

// ---------------------------------------------------------------------------
// 3) gate: one block per row, 16 warps = 16 heads, fused sigmoid
// ---------------------------------------------------------------------------
__global__ __launch_bounds__(512) void gate_kernel(
    const float* __restrict__ xn, const float* __restrict__ gw, float* __restrict__ sg)
{
    int row = blockIdx.x;
    int h = threadIdx.x >> 5;
    int lane = threadIdx.x & 31;
    const float* xr = xn + (size_t)row * DIM;
    const float* wr = gw + (size_t)h * DIM;
    float acc = 0.f;
    #pragma unroll
    for (int i = lane; i < DIM; i += 32) acc = fmaf(xr[i], wr[i], acc);
    #pragma unroll
    for (int o = 16; o > 0; o >>= 1) acc += __shfl_down_sync(0xffffffffu, acc, o);
    if (lane == 0) sg[row * NH + h] = 1.f / (1.f + __expf(-acc));
}

// ---------------------------------------------------------------------------
// 4) q/k per-head RMS norm in place: one warp per (row, q|k, head), 64 elems
// ---------------------------------------------------------------------------
__global__ __launch_bounds__(256) void qknorm_kernel(
    float* __restrict__ qkv, const float* __restrict__ qw, const float* __restrict__ kw)
{
    int w = blockIdx.x * 8 + (threadIdx.x >> 5);   // 0 .. ROWS*32-1
    int lane = threadIdx.x & 31;
    int bs = w >> 5;
    int rem = w & 31;
    int sel = rem >> 4;      // 0 = q, 1 = k
    int h = rem & 15;
    float* p = qkv + (size_t)bs * 3 * DIM + (size_t)sel * DIM + h * HD;
    float v0 = p[lane], v1 = p[lane + 32];
    float ss = v0 * v0 + v1 * v1;
    #pragma unroll
    for (int o = 16; o > 0; o >>= 1) ss += __shfl_xor_sync(0xffffffffu, ss, o);
    float scale = rsqrtf(ss * (1.0f / HD) + EPSV);
    const float* nw = sel ? kw : qw;
    p[lane]      = v0 * scale * nw[lane];
    p[lane + 32] = v1 * scale * nw[lane + 32];
}

// ---------------------------------------------------------------------------
// 5) attention: thread-per-query-row flash. 128 q-rows/block, 64-key tiles.
//    Output written as [b,s,h,d] with sigmoid gate fused.
// ---------------------------------------------------------------------------
__global__ __launch_bounds__(128) void attn_kernel(
    const float* __restrict__ qkv, const float* __restrict__ sg, float* __restrict__ att)
{
    int qt = blockIdx.x & 15;          // 16 q-tiles of 128
    int h  = (blockIdx.x >> 4) & 15;   // head
    int b  = blockIdx.x >> 8;          // batch
    int tid = threadIdx.x;
    int q = qt * 128 + tid;
    size_t bsq = (size_t)b * SQ + q;

    const float4* qrow = (const float4*)(qkv + bsq * 3 * DIM + h * HD);
    float4 qv[16], ov[16];
    #pragma unroll
    for (int i = 0; i < 16; i++) { qv[i] = qrow[i]; ov[i] = make_float4(0,0,0,0); }

    float m = -INFINITY, l = 0.f;
    const float scale = 0.125f;   // 1/sqrt(64)

    __shared__ float4 Ks[64][16];
    __shared__ float4 Vs[64][16];

    for (int kt = 0; kt < SQ; kt += 64) {
        #pragma unroll
        for (int i = tid; i < 64 * 16; i += 128) {
            int r = i >> 4, c = i & 15;
            const float* base = qkv + ((size_t)b * SQ + kt + r) * 3 * DIM + h * HD + c * 4;
            Ks[r][c] = *(const float4*)(base + DIM);
            Vs[r][c] = *(const float4*)(base + 2 * DIM);
        }
        __syncthreads();

        #pragma unroll 1
        for (int ch = 0; ch < 4; ch++) {
            float s[16];
            #pragma unroll 2
            for (int j = 0; j < 16; j++) {
                int jj = ch * 16 + j;
                float acc = 0.f;
                #pragma unroll
                for (int i = 0; i < 16; i++) {
                    float4 kv = Ks[jj][i];
                    acc = fmaf(qv[i].x, kv.x, acc);
                    acc = fmaf(qv[i].y, kv.y, acc);
                    acc = fmaf(qv[i].z, kv.z, acc);
                    acc = fmaf(qv[i].w, kv.w, acc);
                }
                s[j] = acc * scale;
            }
            float mc = s[0];
            #pragma unroll
            for (int j = 1; j < 16; j++) mc = fmaxf(mc, s[j]);
            float mn = fmaxf(m, mc);
            float corr = __expf(m - mn);   // 0 on first chunk (m=-inf)
            l *= corr;
            #pragma unroll
            for (int i = 0; i < 16; i++) {
                ov[i].x *= corr; ov[i].y *= corr; ov[i].z *= corr; ov[i].w *= corr;
            }
            #pragma unroll 2
            for (int j = 0; j < 16; j++) {
                float p = __expf(s[j] - mn);
                l += p;
                int jj = ch * 16 + j;
                #pragma unroll
                for (int i = 0; i < 16; i++) {
                    float4 vv = Vs[jj][i];
                    ov[i].x = fmaf(p, vv.x, ov[i].x);
                    ov[i].y = fmaf(p, vv.y, ov[i].y);
                    ov[i].z = fmaf(p, vv.z, ov[i].z);
                    ov[i].w = fmaf(p, vv.w, ov[i].w);
                }
            }
            m = mn;
        }
        __syncthreads();
    }

    float g = sg[bsq * NH + h];
    float f = g / l;
    float4* orow = (float4*)(att + bsq * DIM + h * HD);
    #pragma unroll
    for (int i = 0; i < 16; i++) {
        ov[i].x *= f; ov[i].y *= f; ov[i].z *= f; ov[i].w *= f;
        orow[i] = ov[i];
    }
}

// ---------------------------------------------------------------------------
// launch
// ---------------------------------------------------------------------------
extern "C" void kernel_launch(void* const* d_in, const int* in_sizes, int n_in,
                              void* d_out, int out_size)
{
    const float* x         = (const float*)d_in[0];
    const float* prenorm_w = (const float*)d_in[1];
    const float* qkv_w     = (const float*)d_in[2];
    const float* gate_w    = (const float*)d_in[3];
    const float* o_w       = (const float*)d_in[4];
    const float* q_norm_w  = (const float*)d_in[5];
    const float* k_norm_w  = (const float*)d_in[6];
    float* out = (float*)d_out;

    float *p_xn, *p_qkv, *p_gate, *p_att;
    cudaGetSymbolAddress((void**)&p_xn,   g_xn);
    cudaGetSymbolAddress((void**)&p_qkv,  g_qkv);
    cudaGetSymbolAddress((void**)&p_gate, g_gate);
    cudaGetSymbolAddress((void**)&p_att,  g_att);

    // 1) prenorm
    prenorm_kernel<<<ROWS, 256>>>(x, prenorm_w, p_xn);

    // 2) QKV GEMM: [4096,1024] x [3072,1024]^T -> [4096,3072]
    sgemm_nt<<<dim3(3 * DIM / 128, ROWS / 128), 256>>>(p_xn, qkv_w, nullptr, p_qkv, 3 * DIM, DIM);

    // 3) gate GEMM + sigmoid
    gate_kernel<<<ROWS, 512>>>(p_xn, gate_w, p_gate);

    // 4) q/k RMS norm in place
    qknorm_kernel<<<ROWS * 32 / 8, 256>>>(p_qkv, q_norm_w, k_norm_w);

    // 5) attention (+ gate) -> [b,s,h,d]
    attn_kernel<<<BATCH * NH * (SQ / 128), 128>>>(p_qkv, p_gate, p_att);

    // 6) O GEMM + residual: [4096,1024] x [1024,1024]^T + x -> out
    sgemm_nt<<<dim3(DIM / 128, ROWS / 128), 256>>>(p_att, o_w, x, out, DIM, DIM);
}

// round 2
// speedup vs baseline: 2.7550x; 2.7550x over previous
#include <cuda_runtime.h>
#include <math.h>
#include <stdint.h>

#define BATCH 2
#define SQ    2048
#define DIM   1024
#define NH    16
#define HD    64
#define ROWS  (BATCH * SQ)   // 4096
#define EPSV  1e-5f

// ---------------------------------------------------------------------------
// Scratch (device globals — allocation rules forbid cudaMalloc)
// ---------------------------------------------------------------------------
__device__ float g_xn[ROWS * DIM];        // prenormed x
__device__ float g_qkv[ROWS * 3 * DIM];   // qkv (q/k rms-normed in place)
__device__ float g_gate[ROWS * NH];       // sigmoid(gate)
__device__ float g_att[ROWS * DIM];       // gated attention out, [b,s,h,d]

// ---------------------------------------------------------------------------
// tf32 helpers
// ---------------------------------------------------------------------------
__device__ __forceinline__ float to_tf32(float x) {
    uint32_t u;
    asm("cvt.rna.tf32.f32 %0, %1;" : "=r"(u) : "f"(x));
    return __uint_as_float(u);
}

__device__ __forceinline__ void mma_tf32(float* d, const float* a, const float* b) {
    asm volatile(
        "mma.sync.aligned.m16n8k8.row.col.f32.tf32.tf32.f32 "
        "{%0,%1,%2,%3},{%4,%5,%6,%7},{%8,%9},{%0,%1,%2,%3};"
        : "+f"(d[0]), "+f"(d[1]), "+f"(d[2]), "+f"(d[3])
        : "r"(__float_as_uint(a[0])), "r"(__float_as_uint(a[1])),
          "r"(__float_as_uint(a[2])), "r"(__float_as_uint(a[3])),
          "r"(__float_as_uint(b[0])), "r"(__float_as_uint(b[1])));
}

// ---------------------------------------------------------------------------
// 1) prenorm RMS: one block per row of 1024
// ---------------------------------------------------------------------------
__global__ __launch_bounds__(256) void prenorm_kernel(
    const float* __restrict__ x, const float* __restrict__ w, float* __restrict__ xn)
{
    int row = blockIdx.x;
    const float* xr = x + (size_t)row * DIM;
    float ss = 0.f;
    #pragma unroll
    for (int i = threadIdx.x; i < DIM; i += 256) { float v = xr[i]; ss += v * v; }
    __shared__ float red[256];
    red[threadIdx.x] = ss;
    __syncthreads();
    for (int s = 128; s > 0; s >>= 1) {
        if (threadIdx.x < s) red[threadIdx.x] += red[threadIdx.x + s];
        __syncthreads();
    }
    float scale = rsqrtf(red[0] * (1.0f / DIM) + EPSV);
    float* xo = xn + (size_t)row * DIM;
    #pragma unroll
    for (int i = threadIdx.x; i < DIM; i += 256) xo[i] = xr[i] * scale * w[i];
}

// ---------------------------------------------------------------------------
// 2) tf32 tensor-core NT GEMM: C[M,N] = A[M,K] * W[N,K]^T (+ optional R)
//    128x128 block tile, BK=16, 256 threads (8 warps, 2m x 4n), warp 64x32
// ---------------------------------------------------------------------------
__global__ __launch_bounds__(256) void sgemm_tf32(
    const float* __restrict__ A, const float* __restrict__ W,
    const float* __restrict__ R, float* __restrict__ C, int N, int K)
{
    __shared__ float As[2][128][20];
    __shared__ float Bs[2][128][20];

    int t = threadIdx.x;
    int warp = t >> 5, lane = t & 31;
    int wm = warp & 1, wn = warp >> 1;       // 2 x 4 warp grid
    int lr = lane >> 2, lq = lane & 3;
    int m0 = blockIdx.y * 128, n0 = blockIdx.x * 128;

    int ldr = t >> 1, ldk = (t & 1) * 8;
    const float* Ag = A + (size_t)(m0 + ldr) * K + ldk;
    const float* Bg = W + (size_t)(n0 + ldr) * K + ldk;

    float c[4][4][4];
    #pragma unroll
    for (int mt = 0; mt < 4; mt++)
        #pragma unroll
        for (int nt = 0; nt < 4; nt++)
            #pragma unroll
            for (int i = 0; i < 4; i++) c[mt][nt][i] = 0.f;

    // preload tile 0
    {
        float4 a0v = *(const float4*)Ag;
        float4 a1v = *(const float4*)(Ag + 4);
        float4 b0v = *(const float4*)Bg;
        float4 b1v = *(const float4*)(Bg + 4);
        *(float4*)&As[0][ldr][ldk]     = make_float4(to_tf32(a0v.x), to_tf32(a0v.y), to_tf32(a0v.z), to_tf32(a0v.w));
        *(float4*)&As[0][ldr][ldk + 4] = make_float4(to_tf32(a1v.x), to_tf32(a1v.y), to_tf32(a1v.z), to_tf32(a1v.w));
        *(float4*)&Bs[0][ldr][ldk]     = make_float4(to_tf32(b0v.x), to_tf32(b0v.y), to_tf32(b0v.z), to_tf32(b0v.w));
        *(float4*)&Bs[0][ldr][ldk + 4] = make_float4(to_tf32(b1v.x), to_tf32(b1v.y), to_tf32(b1v.z), to_tf32(b1v.w));
    }
    __syncthreads();

    int nk = K >> 4;
    for (int kt = 0; kt < nk; kt++) {
        int buf = kt & 1;
        float4 pa0, pa1, pb0, pb1;
        bool pre = (kt + 1 < nk);
        if (pre) {
            const float* ap = Ag + (kt + 1) * 16;
            const float* bp = Bg + (kt + 1) * 16;
            pa0 = *(const float4*)ap; pa1 = *(const float4*)(ap + 4);
            pb0 = *(const float4*)bp; pb1 = *(const float4*)(bp + 4);
        }

        #pragma unroll
        for (int k0 = 0; k0 < 16; k0 += 8) {
            float a[4][4], b[4][2];
            #pragma unroll
            for (int mt = 0; mt < 4; mt++) {
                int r = wm * 64 + mt * 16 + lr;
                a[mt][0] = As[buf][r][k0 + lq];
                a[mt][1] = As[buf][r + 8][k0 + lq];
                a[mt][2] = As[buf][r][k0 + lq + 4];
                a[mt][3] = As[buf][r + 8][k0 + lq + 4];
            }
            #pragma unroll
            for (int nt = 0; nt < 4; nt++) {
                int n = wn * 32 + nt * 8 + lr;
                b[nt][0] = Bs[buf][n][k0 + lq];
                b[nt][1] = Bs[buf][n][k0 + lq + 4];
            }
            #pragma unroll
            for (int mt = 0; mt < 4; mt++)
                #pragma unroll
                for (int nt = 0; nt < 4; nt++)
                    mma_tf32(c[mt][nt], a[mt], b[nt]);
        }

        if (pre) {
            int nb = buf ^ 1;
            *(float4*)&As[nb][ldr][ldk]     = make_float4(to_tf32(pa0.x), to_tf32(pa0.y), to_tf32(pa0.z), to_tf32(pa0.w));
            *(float4*)&As[nb][ldr][ldk + 4] = make_float4(to_tf32(pa1.x), to_tf32(pa1.y), to_tf32(pa1.z), to_tf32(pa1.w));
            *(float4*)&Bs[nb][ldr][ldk]     = make_float4(to_tf32(pb0.x), to_tf32(pb0.y), to_tf32(pb0.z), to_tf32(pb0.w));
            *(float4*)&Bs[nb][ldr][ldk + 4] = make_float4(to_tf32(pb1.x), to_tf32(pb1.y), to_tf32(pb1.z), to_tf32(pb1.w));
            __syncthreads();
        }
    }

    #pragma unroll
    for (int mt = 0; mt < 4; mt++) {
        int row = m0 + wm * 64 + mt * 16 + lr;
        #pragma unroll
        for (int nt = 0; nt < 4; nt++) {
            int col = n0 + wn * 32 + nt * 8 + 2 * lq;
            float2 v0 = make_float2(c[mt][nt][0], c[mt][nt][1]);
            float2 v1 = make_float2(c[mt][nt][2], c[mt][nt][3]);
            if (R) {
                float2 r0 = *(const float2*)(R + (size_t)row * N + col);
                float2 r1 = *(const float2*)(R + (size_t)(row + 8) * N + col);
                v0.x += r0.x; v0.y += r0.y;
                v1.x += r1.x; v1.y += r1.y;
            }
            *(float2*)(C + (size_t)row * N + col) = v0;
            *(float2*)(C + (size_t)(row + 8) * N + col) = v1;
        }
    }
}

// ---------------------------------------------------------------------------
// 3) gate: one block per row, 16 warps = 16 heads, fused sigmoid
// ---------------------------------------------------------------------------
__global__ __launch_bounds__(512) void gate_kernel(
    const float* __restrict__ xn, const float* __restrict__ gw, float* __restrict__ sg)
{
    int row = blockIdx.x;
    int h = threadIdx.x >> 5;
    int lane = threadIdx.x & 31;
    const float* xr = xn + (size_t)row * DIM;
    const float* wr = gw + (size_t)h * DIM;
    float acc = 0.f;
    #pragma unroll
    for (int i = lane; i < DIM; i += 32) acc = fmaf(xr[i], wr[i], acc);
    #pragma unroll
    for (int o = 16; o > 0; o >>= 1) acc += __shfl_down_sync(0xffffffffu, acc, o);
    if (lane == 0) sg[row * NH + h] = 1.f / (1.f + __expf(-acc));
}

// ---------------------------------------------------------------------------
// 4) q/k per-head RMS norm in place: one warp per (row, q|k, head), 64 elems
// ---------------------------------------------------------------------------
__global__ __launch_bounds__(256) void qknorm_kernel(
    float* __restrict__ qkv, const float* __restrict__ qw, const float* __restrict__ kw)
{
    int w = blockIdx.x * 8 + (threadIdx.x >> 5);
    int lane = threadIdx.x & 31;
    int bs = w >> 5;
    int rem = w & 31;
    int sel = rem >> 4;      // 0 = q, 1 = k
    int h = rem & 15;
    float* p = qkv + (size_t)bs * 3 * DIM + (size_t)sel * DIM + h * HD;
    float v0 = p[lane], v1 = p[lane + 32];
    float ss = v0 * v0 + v1 * v1;
    #pragma unroll
    for (int o = 16; o > 0; o >>= 1) ss += __shfl_xor_sync(0xffffffffu, ss, o);
    float scale = rsqrtf(ss * (1.0f / HD) + EPSV);
    const float* nw = sel ? kw : qw;
    p[lane]      = v0 * scale * nw[lane];
    p[lane + 32] = v1 * scale * nw[lane + 32];
}

// ---------------------------------------------------------------------------
// 5) attention (tensor-core flash): block = 64 q-rows, 4 warps x 16 rows.
//    Iterates 64-key tiles; S via mma, online softmax in frags, P through
//    smem (reuses K tile) to re-fragment for PV mma. Gate fused at epilogue.
// ---------------------------------------------------------------------------
__global__ __launch_bounds__(128) void attn_tc(
    const float* __restrict__ qkv, const float* __restrict__ sg, float* __restrict__ att)
{
    __shared__ float Ks[64][68];   // [key][d]; reused as P[qrow(64)][key] mid-iter
    __shared__ float Vs[64][68];   // [d][key]  (transposed)

    int qb = blockIdx.x, h = blockIdx.y, b = blockIdx.z;
    int t = threadIdx.x, warp = t >> 5, lane = t & 31;
    int lr = lane >> 2, lq = lane & 3;

    // Q fragments (scaled by 1/sqrt(64), tf32-converted), rows warp*16 + lr (+8)
    float aQ[8][4];
    {
        int r0 = qb * 64 + warp * 16 + lr;
        const float* Qp  = qkv + ((size_t)(b * SQ) + r0) * (3 * DIM) + h * HD;
        const float* Qp8 = Qp + 8 * (3 * DIM);
        #pragma unroll
        for (int dt = 0; dt < 8; dt++) {
            aQ[dt][0] = to_tf32(Qp [dt * 8 + lq]     * 0.125f);
            aQ[dt][1] = to_tf32(Qp8[dt * 8 + lq]     * 0.125f);
            aQ[dt][2] = to_tf32(Qp [dt * 8 + lq + 4] * 0.125f);
            aQ[dt][3] = to_tf32(Qp8[dt * 8 + lq + 4] * 0.125f);
        }
    }

    float o[8][4];
    #pragma unroll
    for (int nt = 0; nt < 8; nt++)
        #pragma unroll
        for (int i = 0; i < 4; i++) o[nt][i] = 0.f;
    float m0 = -1e30f, m1 = -1e30f, l0 = 0.f, l1 = 0.f;

    // loader mapping: thread t -> key = t&63, half = t>>6 (32 cols)
    int lkey = t & 63, lhalf = t >> 6;
    const float* Kg = qkv + ((size_t)(b * SQ) + lkey) * (3 * DIM) + DIM     + h * HD + lhalf * 32;
    const float* Vg = Kg + DIM;

    for (int s0 = 0; s0 < SQ; s0 += 64) {
        // --- load K tile [key][d] (float4 + cvt) ---
        const float* kg = Kg + (size_t)s0 * (3 * DIM);
        #pragma unroll
        for (int j = 0; j < 32; j += 4) {
            float4 v = *(const float4*)(kg + j);
            *(float4*)&Ks[lkey][lhalf * 32 + j] =
                make_float4(to_tf32(v.x), to_tf32(v.y), to_tf32(v.z), to_tf32(v.w));
        }
        // --- load V tile transposed [d][key] (scalar cvt stores) ---
        const float* vg = Vg + (size_t)s0 * (3 * DIM);
        #pragma unroll
        for (int j = 0; j < 32; j += 4) {
            float4 v = *(const float4*)(vg + j);
            Vs[lhalf * 32 + j + 0][lkey] = to_tf32(v.x);
            Vs[lhalf * 32 + j + 1][lkey] = to_tf32(v.y);
            Vs[lhalf * 32 + j + 2][lkey] = to_tf32(v.z);
            Vs[lhalf * 32 + j + 3][lkey] = to_tf32(v.w);
        }
        __syncthreads();

        // --- scores S[16 x 64] per warp ---
        float sc[8][4];
        #pragma unroll
        for (int nt = 0; nt < 8; nt++)
            #pragma unroll
            for (int i = 0; i < 4; i++) sc[nt][i] = 0.f;

        #pragma unroll
        for (int dt = 0; dt < 8; dt++) {
            #pragma unroll
            for (int nt = 0; nt < 8; nt++) {
                float bfr[2];
                bfr[0] = Ks[nt * 8 + lr][dt * 8 + lq];
                bfr[1] = Ks[nt * 8 + lr][dt * 8 + lq + 4];
                mma_tf32(sc[nt], aQ[dt], bfr);
            }
        }

        // --- online softmax (rows r0 = lane/4, r1 = r0+8) ---
        float rm0 = sc[0][0], rm1 = sc[0][2];
        #pragma unroll
        for (int nt = 0; nt < 8; nt++) {
            rm0 = fmaxf(rm0, fmaxf(sc[nt][0], sc[nt][1]));
            rm1 = fmaxf(rm1, fmaxf(sc[nt][2], sc[nt][3]));
        }
        rm0 = fmaxf(rm0, __shfl_xor_sync(0xffffffffu, rm0, 1));
        rm0 = fmaxf(rm0, __shfl_xor_sync(0xffffffffu, rm0, 2));
        rm1 = fmaxf(rm1, __shfl_xor_sync(0xffffffffu, rm1, 1));
        rm1 = fmaxf(rm1, __shfl_xor_sync(0xffffffffu, rm1, 2));
        float mn0 = fmaxf(m0, rm0), mn1 = fmaxf(m1, rm1);
        float co0 = __expf(m0 - mn0), co1 = __expf(m1 - mn1);
        float sum0 = 0.f, sum1 = 0.f;
        #pragma unroll
        for (int nt = 0; nt < 8; nt++) {
            sc[nt][0] = __expf(sc[nt][0] - mn0);
            sc[nt][1] = __expf(sc[nt][1] - mn0);
            sc[nt][2] = __expf(sc[nt][2] - mn1);
            sc[nt][3] = __expf(sc[nt][3] - mn1);
            sum0 += sc[nt][0] + sc[nt][1];
            sum1 += sc[nt][2] + sc[nt][3];
        }
        sum0 += __shfl_xor_sync(0xffffffffu, sum0, 1);
        sum0 += __shfl_xor_sync(0xffffffffu, sum0, 2);
        sum1 += __shfl_xor_sync(0xffffffffu, sum1, 1);
        sum1 += __shfl_xor_sync(0xffffffffu, sum1, 2);
        l0 = l0 * co0 + sum0;
        l1 = l1 * co1 + sum1;
        #pragma unroll
        for (int nt = 0; nt < 8; nt++) {
            o[nt][0] *= co0; o[nt][1] *= co0;
            o[nt][2] *= co1; o[nt][3] *= co1;
        }
        m0 = mn0; m1 = mn1;

        __syncthreads();   // all warps done reading Ks -> safe to overwrite with P

        // --- store P into Ks region: P[warp*16 + r][key] (tf32) ---
        {
            int pr0 = warp * 16 + lr, pr1 = pr0 + 8;
            #pragma unroll
            for (int nt = 0; nt < 8; nt++) {
                int colp = nt * 8 + 2 * lq;
                *(float2*)&Ks[pr0][colp] = make_float2(to_tf32(sc[nt][0]), to_tf32(sc[nt][1]));
                *(float2*)&Ks[pr1][colp] = make_float2(to_tf32(sc[nt][2]), to_tf32(sc[nt][3]));
            }
        }
        __syncwarp();

        // --- PV: O[16 x 64] += P[16 x 64] * V[64 x 64] ---
        #pragma unroll
        for (int kt = 0; kt < 8; kt++) {
            float a[4];
            int pr0 = warp * 16 + lr;
            a[0] = Ks[pr0][kt * 8 + lq];
            a[1] = Ks[pr0 + 8][kt * 8 + lq];
            a[2] = Ks[pr0][kt * 8 + lq + 4];
            a[3] = Ks[pr0 + 8][kt * 8 + lq + 4];
            #pragma unroll
            for (int nt = 0; nt < 8; nt++) {
                float bfr[2];
                bfr[0] = Vs[nt * 8 + lr][kt * 8 + lq];
                bfr[1] = Vs[nt * 8 + lr][kt * 8 + lq + 4];
                mma_tf32(o[nt], a, bfr);
            }
        }
        __syncthreads();   // all warps done reading Vs (and P) before next tile load
    }

    // --- epilogue: normalize, gate, store [b,s,h,d] ---
    int r0 = qb * 64 + warp * 16 + lr;
    int r1 = r0 + 8;
    float g0 = sg[((size_t)(b * SQ) + r0) * NH + h];
    float g1 = sg[((size_t)(b * SQ) + r1) * NH + h];
    float f0 = g0 / l0, f1 = g1 / l1;
    float* o0 = att + ((size_t)(b * SQ) + r0) * DIM + h * HD;
    float* o1 = att + ((size_t)(b * SQ) + r1) * DIM + h * HD;
    #pragma unroll
    for (int nt = 0; nt < 8; nt++) {
        int col = nt * 8 + 2 * lq;
        *(float2*)(o0 + col) = make_float2(o[nt][0] * f0, o[nt][1] * f0);
        *(float2*)(o1 + col) = make_float2(o[nt][2] * f1, o[nt][3] * f1);
    }
}

// ---------------------------------------------------------------------------
// launch
// ---------------------------------------------------------------------------
extern "C" void kernel_launch(void* const* d_in, const int* in_sizes, int n_in,
                              void* d_out, int out_size)
{
    const float* x         = (const float*)d_in[0];
    const float* prenorm_w = (const float*)d_in[1];
    const float* qkv_w     = (const float*)d_in[2];
    const float* gate_w    = (const float*)d_in[3];
    const float* o_w       = (const float*)d_in[4];
    const float* q_norm_w  = (const float*)d_in[5];
    const float* k_norm_w  = (const float*)d_in[6];
    float* out = (float*)d_out;

    float *p_xn, *p_qkv, *p_gate, *p_att;
    cudaGetSymbolAddress((void**)&p_xn,   g_xn);
    cudaGetSymbolAddress((void**)&p_qkv,  g_qkv);
    cudaGetSymbolAddress((void**)&p_gate, g_gate);
    cudaGetSymbolAddress((void**)&p_att,  g_att);

    // 1) prenorm
    prenorm_kernel<<<ROWS, 256>>>(x, prenorm_w, p_xn);

    // 2) QKV GEMM (tf32 TC): [4096,1024] x [3072,1024]^T -> [4096,3072]
    sgemm_tf32<<<dim3(3 * DIM / 128, ROWS / 128), 256>>>(p_xn, qkv_w, nullptr, p_qkv, 3 * DIM, DIM);

    // 3) gate GEMM + sigmoid
    gate_kernel<<<ROWS, 512>>>(p_xn, gate_w, p_gate);

    // 4) q/k RMS norm in place
    qknorm_kernel<<<ROWS * 32 / 8, 256>>>(p_qkv, q_norm_w, k_norm_w);

    // 5) attention (tf32 TC flash + gate) -> [b,s,h,d]
    attn_tc<<<dim3(SQ / 64, NH, BATCH), 128>>>(p_qkv, p_gate, p_att);

    // 6) O GEMM + residual (tf32 TC): [4096,1024] x [1024,1024]^T + x -> out
    sgemm_tf32<<<dim3(DIM / 128, ROWS / 128), 256>>>(p_att, o_w, x, out, DIM, DIM);
}

// round 3
// speedup vs baseline: 3.7597x; 1.3647x over previous
#include <cuda_runtime.h>
#include <cuda_fp16.h>
#include <math.h>
#include <stdint.h>

#define BATCH 2
#define SQ    2048
#define DIM   1024
#define NH    16
#define HD    64
#define ROWS  (BATCH * SQ)   // 4096
#define EPSV  1e-5f

// ---------------------------------------------------------------------------
// Scratch (device globals)
// ---------------------------------------------------------------------------
__device__ __half g_xnh[ROWS * DIM];          // prenormed x (fp16)
__device__ __half g_qkvh[ROWS * 3 * DIM];     // qkv fp16 (q/k rms-normed in place)
__device__ __half g_atth[ROWS * DIM];         // gated attention out fp16, [b,s,h,d]
__device__ float  g_gate[ROWS * NH];          // sigmoid(gate)
__device__ __half g_qkv_wh[3 * DIM * DIM];
__device__ __half g_o_wh[DIM * DIM];
__device__ __half g_gate_wh[NH * DIM];

// ---------------------------------------------------------------------------
// fp16 mma helper: m16n8k16, fp32 accumulate
// ---------------------------------------------------------------------------
__device__ __forceinline__ void mma_f16(float* d, const uint32_t* a, const uint32_t* b) {
    asm volatile(
        "mma.sync.aligned.m16n8k16.row.col.f32.f16.f16.f32 "
        "{%0,%1,%2,%3},{%4,%5,%6,%7},{%8,%9},{%0,%1,%2,%3};"
        : "+f"(d[0]), "+f"(d[1]), "+f"(d[2]), "+f"(d[3])
        : "r"(a[0]), "r"(a[1]), "r"(a[2]), "r"(a[3]), "r"(b[0]), "r"(b[1]));
}

__device__ __forceinline__ uint32_t h2u(__half2 v) { return *(uint32_t*)&v; }

// ---------------------------------------------------------------------------
// 0) weight conversion fp32 -> fp16
// ---------------------------------------------------------------------------
#define QKV_WN (3 * DIM * DIM)
#define O_WN   (DIM * DIM)
#define G_WN   (NH * DIM)

__global__ __launch_bounds__(256) void convert_w(
    const float* __restrict__ qkv_w, const float* __restrict__ o_w,
    const float* __restrict__ gate_w,
    __half* __restrict__ qkv_wh, __half* __restrict__ o_wh, __half* __restrict__ gate_wh)
{
    int i = (blockIdx.x * 256 + threadIdx.x) * 4;
    const float* src;
    __half* dst;
    if (i < QKV_WN)                { src = qkv_w + i;               dst = qkv_wh + i; }
    else if (i < QKV_WN + O_WN)    { src = o_w + (i - QKV_WN);      dst = o_wh + (i - QKV_WN); }
    else if (i < QKV_WN + O_WN + G_WN) { src = gate_w + (i - QKV_WN - O_WN); dst = gate_wh + (i - QKV_WN - O_WN); }
    else return;
    float4 v = *(const float4*)src;
    *(__half2*)(dst)     = __floats2half2_rn(v.x, v.y);
    *(__half2*)(dst + 2) = __floats2half2_rn(v.z, v.w);
}

// ---------------------------------------------------------------------------
// 1) prenorm RMS -> fp16 out
// ---------------------------------------------------------------------------
__global__ __launch_bounds__(256) void prenorm_kernel(
    const float* __restrict__ x, const float* __restrict__ w, __half* __restrict__ xn)
{
    int row = blockIdx.x;
    const float* xr = x + (size_t)row * DIM;
    float ss = 0.f;
    #pragma unroll
    for (int i = threadIdx.x; i < DIM; i += 256) { float v = xr[i]; ss += v * v; }
    __shared__ float red[256];
    red[threadIdx.x] = ss;
    __syncthreads();
    for (int s = 128; s > 0; s >>= 1) {
        if (threadIdx.x < s) red[threadIdx.x] += red[threadIdx.x + s];
        __syncthreads();
    }
    float scale = rsqrtf(red[0] * (1.0f / DIM) + EPSV);
    __half* xo = xn + (size_t)row * DIM;
    #pragma unroll
    for (int i = threadIdx.x; i < DIM; i += 256) xo[i] = __float2half(xr[i] * scale * w[i]);
}

// ---------------------------------------------------------------------------
// 2) fp16 NT GEMM: C[M,N] = A[M,K] * W[N,K]^T
//    128x128 tile, BK=32, 256 threads (8 warps 2x4), warp 64x32
//    MODE 0: C fp16; MODE 1: C fp32 with fp32 residual R
// ---------------------------------------------------------------------------
#define BKP 40   // 32 + 8 pad (halves)

template<int MODE>
__global__ __launch_bounds__(256) void hgemm_nt(
    const __half* __restrict__ A, const __half* __restrict__ W,
    const float* __restrict__ R, void* __restrict__ Cv, int N, int K)
{
    __shared__ __half As[2][128][BKP];
    __shared__ __half Bs[2][128][BKP];

    int t = threadIdx.x;
    int warp = t >> 5, lane = t & 31;
    int wm = warp & 1, wn = warp >> 1;
    int lr = lane >> 2, lq = lane & 3;
    int m0 = blockIdx.y * 128, n0 = blockIdx.x * 128;

    int ldr = t >> 1, ldh = (t & 1) * 16;
    const __half* Ag = A + (size_t)(m0 + ldr) * K + ldh;
    const __half* Bg = W + (size_t)(n0 + ldr) * K + ldh;

    float c[4][4][4];
    #pragma unroll
    for (int mt = 0; mt < 4; mt++)
        #pragma unroll
        for (int nt = 0; nt < 4; nt++)
            #pragma unroll
            for (int i = 0; i < 4; i++) c[mt][nt][i] = 0.f;

    // preload tile 0
    {
        uint4 a0 = *(const uint4*)Ag, a1 = *(const uint4*)(Ag + 8);
        uint4 b0 = *(const uint4*)Bg, b1 = *(const uint4*)(Bg + 8);
        uint2* pa = (uint2*)&As[0][ldr][ldh];
        uint2* pb = (uint2*)&Bs[0][ldr][ldh];
        pa[0] = make_uint2(a0.x, a0.y); pa[1] = make_uint2(a0.z, a0.w);
        pa[2] = make_uint2(a1.x, a1.y); pa[3] = make_uint2(a1.z, a1.w);
        pb[0] = make_uint2(b0.x, b0.y); pb[1] = make_uint2(b0.z, b0.w);
        pb[2] = make_uint2(b1.x, b1.y); pb[3] = make_uint2(b1.z, b1.w);
    }
    __syncthreads();

    int nk = K >> 5;
    for (int kt = 0; kt < nk; kt++) {
        int buf = kt & 1;
        uint4 pa0, pa1, pb0, pb1;
        bool pre = (kt + 1 < nk);
        if (pre) {
            const __half* ap = Ag + (kt + 1) * 32;
            const __half* bp = Bg + (kt + 1) * 32;
            pa0 = *(const uint4*)ap; pa1 = *(const uint4*)(ap + 8);
            pb0 = *(const uint4*)bp; pb1 = *(const uint4*)(bp + 8);
        }

        #pragma unroll
        for (int k0 = 0; k0 < 32; k0 += 16) {
            uint32_t a[4][4], b[4][2];
            #pragma unroll
            for (int mt = 0; mt < 4; mt++) {
                int r = wm * 64 + mt * 16 + lr;
                a[mt][0] = *(uint32_t*)&As[buf][r][k0 + 2 * lq];
                a[mt][1] = *(uint32_t*)&As[buf][r + 8][k0 + 2 * lq];
                a[mt][2] = *(uint32_t*)&As[buf][r][k0 + 8 + 2 * lq];
                a[mt][3] = *(uint32_t*)&As[buf][r + 8][k0 + 8 + 2 * lq];
            }
            #pragma unroll
            for (int nt = 0; nt < 4; nt++) {
                int n = wn * 32 + nt * 8 + lr;
                b[nt][0] = *(uint32_t*)&Bs[buf][n][k0 + 2 * lq];
                b[nt][1] = *(uint32_t*)&Bs[buf][n][k0 + 8 + 2 * lq];
            }
            #pragma unroll
            for (int mt = 0; mt < 4; mt++)
                #pragma unroll
                for (int nt = 0; nt < 4; nt++)
                    mma_f16(c[mt][nt], a[mt], b[nt]);
        }

        if (pre) {
            int nb = buf ^ 1;
            uint2* pa = (uint2*)&As[nb][ldr][ldh];
            uint2* pb = (uint2*)&Bs[nb][ldr][ldh];
            pa[0] = make_uint2(pa0.x, pa0.y); pa[1] = make_uint2(pa0.z, pa0.w);
            pa[2] = make_uint2(pa1.x, pa1.y); pa[3] = make_uint2(pa1.z, pa1.w);
            pb[0] = make_uint2(pb0.x, pb0.y); pb[1] = make_uint2(pb0.z, pb0.w);
            pb[2] = make_uint2(pb1.x, pb1.y); pb[3] = make_uint2(pb1.z, pb1.w);
            __syncthreads();
        }
    }

    #pragma unroll
    for (int mt = 0; mt < 4; mt++) {
        int row = m0 + wm * 64 + mt * 16 + lr;
        #pragma unroll
        for (int nt = 0; nt < 4; nt++) {
            int col = n0 + wn * 32 + nt * 8 + 2 * lq;
            if (MODE == 0) {
                __half* C = (__half*)Cv;
                *(__half2*)(C + (size_t)row * N + col)       = __floats2half2_rn(c[mt][nt][0], c[mt][nt][1]);
                *(__half2*)(C + (size_t)(row + 8) * N + col) = __floats2half2_rn(c[mt][nt][2], c[mt][nt][3]);
            } else {
                float* C = (float*)Cv;
                float2 r0 = *(const float2*)(R + (size_t)row * N + col);
                float2 r1 = *(const float2*)(R + (size_t)(row + 8) * N + col);
                *(float2*)(C + (size_t)row * N + col)       = make_float2(c[mt][nt][0] + r0.x, c[mt][nt][1] + r0.y);
                *(float2*)(C + (size_t)(row + 8) * N + col) = make_float2(c[mt][nt][2] + r1.x, c[mt][nt][3] + r1.y);
            }
        }
    }
}

// ---------------------------------------------------------------------------
// 3) gate: one block per row, 16 warps = 16 heads, fused sigmoid (fp16 in)
// ---------------------------------------------------------------------------
__global__ __launch_bounds__(512) void gate_kernel(
    const __half* __restrict__ xn, const __half* __restrict__ gw, float* __restrict__ sg)
{
    int row = blockIdx.x;
    int h = threadIdx.x >> 5;
    int lane = threadIdx.x & 31;
    const __half2* xr = (const __half2*)(xn + (size_t)row * DIM);
    const __half2* wr = (const __half2*)(gw + (size_t)h * DIM);
    float acc = 0.f;
    #pragma unroll
    for (int i = lane; i < DIM / 2; i += 32) {
        float2 a = __half22float2(xr[i]);
        float2 b = __half22float2(wr[i]);
        acc = fmaf(a.x, b.x, acc);
        acc = fmaf(a.y, b.y, acc);
    }
    #pragma unroll
    for (int o = 16; o > 0; o >>= 1) acc += __shfl_down_sync(0xffffffffu, acc, o);
    if (lane == 0) sg[row * NH + h] = 1.f / (1.f + __expf(-acc));
}

// ---------------------------------------------------------------------------
// 4) q/k per-head RMS norm in place (fp16): warp per (row, q|k, head)
// ---------------------------------------------------------------------------
__global__ __launch_bounds__(256) void qknorm_kernel(
    __half* __restrict__ qkv, const float* __restrict__ qw, const float* __restrict__ kw)
{
    int w = blockIdx.x * 8 + (threadIdx.x >> 5);
    int lane = threadIdx.x & 31;
    int bs = w >> 5;
    int rem = w & 31;
    int sel = rem >> 4;
    int h = rem & 15;
    __half2* p = (__half2*)(qkv + (size_t)bs * 3 * DIM + (size_t)sel * DIM + h * HD);
    float2 v = __half22float2(p[lane]);
    float ss = v.x * v.x + v.y * v.y;
    #pragma unroll
    for (int o = 16; o > 0; o >>= 1) ss += __shfl_xor_sync(0xffffffffu, ss, o);
    float scale = rsqrtf(ss * (1.0f / HD) + EPSV);
    const float* nw = sel ? kw : qw;
    p[lane] = __floats2half2_rn(v.x * scale * nw[2 * lane], v.y * scale * nw[2 * lane + 1]);
}

// ---------------------------------------------------------------------------
// 5) attention (fp16 TC flash): block = 64 q-rows, 4 warps x 16 rows.
//    P stays in registers (k16 = 2 x n8 alignment). Gate fused at epilogue.
// ---------------------------------------------------------------------------
__global__ __launch_bounds__(128) void attn_f16(
    const __half* __restrict__ qkv, const float* __restrict__ sg, __half* __restrict__ att)
{
    __shared__ __half Ks[64][72];   // [key][d]
    __shared__ __half Vs[64][72];   // [d][key] (transposed)

    int qb = blockIdx.x, h = blockIdx.y, b = blockIdx.z;
    int t = threadIdx.x, warp = t >> 5, lane = t & 31;
    int lr = lane >> 2, lq = lane & 3;

    // Q fragments, pre-scaled by 1/8 (exact in fp16)
    uint32_t aQ[4][4];
    {
        int r0 = qb * 64 + warp * 16 + lr;
        const __half* Qp  = qkv + ((size_t)(b * SQ) + r0) * (3 * DIM) + h * HD;
        const __half* Qp8 = Qp + 8 * (3 * DIM);
        __half2 s8 = __floats2half2_rn(0.125f, 0.125f);
        #pragma unroll
        for (int dt = 0; dt < 4; dt++) {
            __half2 v;
            v = __hmul2(*(const __half2*)(Qp  + dt * 16 + 2 * lq), s8);     aQ[dt][0] = h2u(v);
            v = __hmul2(*(const __half2*)(Qp8 + dt * 16 + 2 * lq), s8);     aQ[dt][1] = h2u(v);
            v = __hmul2(*(const __half2*)(Qp  + dt * 16 + 8 + 2 * lq), s8); aQ[dt][2] = h2u(v);
            v = __hmul2(*(const __half2*)(Qp8 + dt * 16 + 8 + 2 * lq), s8); aQ[dt][3] = h2u(v);
        }
    }

    float o[8][4];
    #pragma unroll
    for (int nt = 0; nt < 8; nt++)
        #pragma unroll
        for (int i = 0; i < 4; i++) o[nt][i] = 0.f;
    float m0 = -1e30f, m1 = -1e30f, l0 = 0.f, l1 = 0.f;

    int lkey = t & 63, lhalf = t >> 6;   // thread covers 32 d-vals of one key
    const __half* Kg = qkv + ((size_t)(b * SQ) + lkey) * (3 * DIM) + DIM + h * HD + lhalf * 32;
    const __half* Vg = Kg + DIM;

    for (int s0 = 0; s0 < SQ; s0 += 64) {
        // K tile [key][d]
        const __half* kg = Kg + (size_t)s0 * (3 * DIM);
        #pragma unroll
        for (int j = 0; j < 4; j++) {
            uint4 v = *(const uint4*)(kg + j * 8);
            uint2* pk = (uint2*)&Ks[lkey][lhalf * 32 + j * 8];
            pk[0] = make_uint2(v.x, v.y); pk[1] = make_uint2(v.z, v.w);
        }
        // V tile transposed [d][key]
        const __half* vg = Vg + (size_t)s0 * (3 * DIM);
        #pragma unroll
        for (int j = 0; j < 32; j += 2) {
            __half2 v = *(const __half2*)(vg + j);
            Vs[lhalf * 32 + j][lkey]     = __low2half(v);
            Vs[lhalf * 32 + j + 1][lkey] = __high2half(v);
        }
        __syncthreads();

        // S = Q K^T  (16 x 64 per warp)
        float sc[8][4];
        #pragma unroll
        for (int nt = 0; nt < 8; nt++)
            #pragma unroll
            for (int i = 0; i < 4; i++) sc[nt][i] = 0.f;

        #pragma unroll
        for (int dt = 0; dt < 4; dt++) {
            #pragma unroll
            for (int nt = 0; nt < 8; nt++) {
                uint32_t bf[2];
                bf[0] = *(uint32_t*)&Ks[nt * 8 + lr][dt * 16 + 2 * lq];
                bf[1] = *(uint32_t*)&Ks[nt * 8 + lr][dt * 16 + 8 + 2 * lq];
                mma_f16(sc[nt], aQ[dt], bf);
            }
        }

        // online softmax (rows lr, lr+8)
        float rm0 = sc[0][0], rm1 = sc[0][2];
        #pragma unroll
        for (int nt = 0; nt < 8; nt++) {
            rm0 = fmaxf(rm0, fmaxf(sc[nt][0], sc[nt][1]));
            rm1 = fmaxf(rm1, fmaxf(sc[nt][2], sc[nt][3]));
        }
        rm0 = fmaxf(rm0, __shfl_xor_sync(0xffffffffu, rm0, 1));
        rm0 = fmaxf(rm0, __shfl_xor_sync(0xffffffffu, rm0, 2));
        rm1 = fmaxf(rm1, __shfl_xor_sync(0xffffffffu, rm1, 1));
        rm1 = fmaxf(rm1, __shfl_xor_sync(0xffffffffu, rm1, 2));
        float mn0 = fmaxf(m0, rm0), mn1 = fmaxf(m1, rm1);
        float co0 = __expf(m0 - mn0), co1 = __expf(m1 - mn1);
        float sum0 = 0.f, sum1 = 0.f;
        #pragma unroll
        for (int nt = 0; nt < 8; nt++) {
            sc[nt][0] = __expf(sc[nt][0] - mn0);
            sc[nt][1] = __expf(sc[nt][1] - mn0);
            sc[nt][2] = __expf(sc[nt][2] - mn1);
            sc[nt][3] = __expf(sc[nt][3] - mn1);
            sum0 += sc[nt][0] + sc[nt][1];
            sum1 += sc[nt][2] + sc[nt][3];
        }
        sum0 += __shfl_xor_sync(0xffffffffu, sum0, 1);
        sum0 += __shfl_xor_sync(0xffffffffu, sum0, 2);
        sum1 += __shfl_xor_sync(0xffffffffu, sum1, 1);
        sum1 += __shfl_xor_sync(0xffffffffu, sum1, 2);
        l0 = l0 * co0 + sum0;
        l1 = l1 * co1 + sum1;
        #pragma unroll
        for (int nt = 0; nt < 8; nt++) {
            o[nt][0] *= co0; o[nt][1] *= co0;
            o[nt][2] *= co1; o[nt][3] *= co1;
        }
        m0 = mn0; m1 = mn1;

        // PV: P in registers (C-frag of S == A-frag for k16)
        #pragma unroll
        for (int kt = 0; kt < 4; kt++) {
            uint32_t aP[4];
            __half2 v;
            v = __floats2half2_rn(sc[2 * kt][0],     sc[2 * kt][1]);     aP[0] = h2u(v);
            v = __floats2half2_rn(sc[2 * kt][2],     sc[2 * kt][3]);     aP[1] = h2u(v);
            v = __floats2half2_rn(sc[2 * kt + 1][0], sc[2 * kt + 1][1]); aP[2] = h2u(v);
            v = __floats2half2_rn(sc[2 * kt + 1][2], sc[2 * kt + 1][3]); aP[3] = h2u(v);
            #pragma unroll
            for (int nt = 0; nt < 8; nt++) {
                uint32_t bf[2];
                bf[0] = *(uint32_t*)&Vs[nt * 8 + lr][kt * 16 + 2 * lq];
                bf[1] = *(uint32_t*)&Vs[nt * 8 + lr][kt * 16 + 8 + 2 * lq];
                mma_f16(o[nt], aP, bf);
            }
        }
        __syncthreads();   // protect Ks/Vs before next tile load
    }

    // epilogue: normalize, gate, store fp16 [b,s,h,d]
    int r0 = qb * 64 + warp * 16 + lr;
    int r1 = r0 + 8;
    float g0 = sg[((size_t)(b * SQ) + r0) * NH + h];
    float g1 = sg[((size_t)(b * SQ) + r1) * NH + h];
    float f0 = g0 / l0, f1 = g1 / l1;
    __half* o0 = att + ((size_t)(b * SQ) + r0) * DIM + h * HD;
    __half* o1 = att + ((size_t)(b * SQ) + r1) * DIM + h * HD;
    #pragma unroll
    for (int nt = 0; nt < 8; nt++) {
        int col = nt * 8 + 2 * lq;
        *(__half2*)(o0 + col) = __floats2half2_rn(o[nt][0] * f0, o[nt][1] * f0);
        *(__half2*)(o1 + col) = __floats2half2_rn(o[nt][2] * f1, o[nt][3] * f1);
    }
}

// ---------------------------------------------------------------------------
// launch
// ---------------------------------------------------------------------------
extern "C" void kernel_launch(void* const* d_in, const int* in_sizes, int n_in,
                              void* d_out, int out_size)
{
    const float* x         = (const float*)d_in[0];
    const float* prenorm_w = (const float*)d_in[1];
    const float* qkv_w     = (const float*)d_in[2];
    const float* gate_w    = (const float*)d_in[3];
    const float* o_w       = (const float*)d_in[4];
    const float* q_norm_w  = (const float*)d_in[5];
    const float* k_norm_w  = (const float*)d_in[6];
    float* out = (float*)d_out;

    __half *p_xnh, *p_qkvh, *p_atth, *p_qkv_wh, *p_o_wh, *p_gate_wh;
    float *p_gate;
    cudaGetSymbolAddress((void**)&p_xnh,    g_xnh);
    cudaGetSymbolAddress((void**)&p_qkvh,   g_qkvh);
    cudaGetSymbolAddress((void**)&p_atth,   g_atth);
    cudaGetSymbolAddress((void**)&p_gate,   g_gate);
    cudaGetSymbolAddress((void**)&p_qkv_wh, g_qkv_wh);
    cudaGetSymbolAddress((void**)&p_o_wh,   g_o_wh);
    cudaGetSymbolAddress((void**)&p_gate_wh,g_gate_wh);

    // 0) weights -> fp16
    int wtot4 = (QKV_WN + O_WN + G_WN) / 4;
    convert_w<<<(wtot4 + 255) / 256, 256>>>(qkv_w, o_w, gate_w, p_qkv_wh, p_o_wh, p_gate_wh);

    // 1) prenorm -> fp16
    prenorm_kernel<<<ROWS, 256>>>(x, prenorm_w, p_xnh);

    // 2) QKV GEMM (fp16 TC)
    hgemm_nt<0><<<dim3(3 * DIM / 128, ROWS / 128), 256>>>(p_xnh, p_qkv_wh, nullptr, p_qkvh, 3 * DIM, DIM);

    // 3) gate + sigmoid
    gate_kernel<<<ROWS, 512>>>(p_xnh, p_gate_wh, p_gate);

    // 4) q/k RMS norm in place
    qknorm_kernel<<<ROWS * 32 / 8, 256>>>(p_qkvh, q_norm_w, k_norm_w);

    // 5) attention (fp16 TC flash + gate)
    attn_f16<<<dim3(SQ / 64, NH, BATCH), 128>>>(p_qkvh, p_gate, p_atth);

    // 6) O GEMM + residual -> fp32 out
    hgemm_nt<1><<<dim3(DIM / 128, ROWS / 128), 256>>>(p_atth, p_o_wh, x, out, DIM, DIM);
}

// round 4
// speedup vs baseline: 6.4670x; 1.7201x over previous
#include <cuda_runtime.h>
#include <cuda_fp16.h>
#include <math.h>
#include <stdint.h>

#define BATCH 2
#define SQ    2048
#define DIM   1024
#define NH    16
#define HD    64
#define ROWS  (BATCH * SQ)   // 4096
#define EPSV  1e-5f

// ---------------------------------------------------------------------------
// Scratch (device globals)
// ---------------------------------------------------------------------------
__device__ __half g_xnh[ROWS * DIM];
__device__ __half g_qkvh[ROWS * 3 * DIM];
__device__ __half g_atth[ROWS * DIM];
__device__ float  g_gate[ROWS * NH];
__device__ __half g_qkv_wh[3 * DIM * DIM];
__device__ __half g_o_wh[DIM * DIM];
__device__ __half g_gate_wh[NH * DIM];

// ---------------------------------------------------------------------------
// PTX helpers
// ---------------------------------------------------------------------------
__device__ __forceinline__ void mma_f16(float* d, const uint32_t* a, uint32_t b0, uint32_t b1) {
    asm volatile(
        "mma.sync.aligned.m16n8k16.row.col.f32.f16.f16.f32 "
        "{%0,%1,%2,%3},{%4,%5,%6,%7},{%8,%9},{%0,%1,%2,%3};"
        : "+f"(d[0]), "+f"(d[1]), "+f"(d[2]), "+f"(d[3])
        : "r"(a[0]), "r"(a[1]), "r"(a[2]), "r"(a[3]), "r"(b0), "r"(b1));
}

__device__ __forceinline__ uint32_t h2u(__half2 v) { return *(uint32_t*)&v; }
__device__ __forceinline__ uint32_t smem_u32(const void* p) {
    return (uint32_t)__cvta_generic_to_shared(p);
}

#define LDSM_X4(r0, r1, r2, r3, addr) \
    asm volatile("ldmatrix.sync.aligned.m8n8.x4.shared.b16 {%0,%1,%2,%3},[%4];" \
        : "=r"(r0), "=r"(r1), "=r"(r2), "=r"(r3) : "r"(addr))

#define LDSM_X4T(r0, r1, r2, r3, addr) \
    asm volatile("ldmatrix.sync.aligned.m8n8.x4.trans.shared.b16 {%0,%1,%2,%3},[%4];" \
        : "=r"(r0), "=r"(r1), "=r"(r2), "=r"(r3) : "r"(addr))

#define CP16(smem, gptr) \
    asm volatile("cp.async.cg.shared.global [%0], [%1], 16;" :: "r"(smem), "l"(gptr))
#define CP_COMMIT() asm volatile("cp.async.commit_group;")
#define CP_WAIT0()  asm volatile("cp.async.wait_group 0;")

// ---------------------------------------------------------------------------
// 0) weight conversion fp32 -> fp16
// ---------------------------------------------------------------------------
#define QKV_WN (3 * DIM * DIM)
#define O_WN   (DIM * DIM)
#define G_WN   (NH * DIM)

__global__ __launch_bounds__(256) void convert_w(
    const float* __restrict__ qkv_w, const float* __restrict__ o_w,
    const float* __restrict__ gate_w,
    __half* __restrict__ qkv_wh, __half* __restrict__ o_wh, __half* __restrict__ gate_wh)
{
    int i = (blockIdx.x * 256 + threadIdx.x) * 4;
    const float* src;
    __half* dst;
    if (i < QKV_WN)                    { src = qkv_w + i;                   dst = qkv_wh + i; }
    else if (i < QKV_WN + O_WN)        { src = o_w + (i - QKV_WN);          dst = o_wh + (i - QKV_WN); }
    else if (i < QKV_WN + O_WN + G_WN) { src = gate_w + (i - QKV_WN - O_WN); dst = gate_wh + (i - QKV_WN - O_WN); }
    else return;
    float4 v = *(const float4*)src;
    *(__half2*)(dst)     = __floats2half2_rn(v.x, v.y);
    *(__half2*)(dst + 2) = __floats2half2_rn(v.z, v.w);
}

// ---------------------------------------------------------------------------
// 1) prenorm RMS -> fp16 out
// ---------------------------------------------------------------------------
__global__ __launch_bounds__(256) void prenorm_kernel(
    const float* __restrict__ x, const float* __restrict__ w, __half* __restrict__ xn)
{
    int row = blockIdx.x;
    const float* xr = x + (size_t)row * DIM;
    float ss = 0.f;
    #pragma unroll
    for (int i = threadIdx.x; i < DIM; i += 256) { float v = xr[i]; ss += v * v; }
    __shared__ float red[256];
    red[threadIdx.x] = ss;
    __syncthreads();
    for (int s = 128; s > 0; s >>= 1) {
        if (threadIdx.x < s) red[threadIdx.x] += red[threadIdx.x + s];
        __syncthreads();
    }
    float scale = rsqrtf(red[0] * (1.0f / DIM) + EPSV);
    __half* xo = xn + (size_t)row * DIM;
    #pragma unroll
    for (int i = threadIdx.x; i < DIM; i += 256) xo[i] = __float2half(xr[i] * scale * w[i]);
}

// ---------------------------------------------------------------------------
// 2) fp16 NT GEMM with ldmatrix fragment loads
//    128x128 tile, BK=32, 256 threads (8 warps 2x4), warp 64x32
// ---------------------------------------------------------------------------
#define BKP 40   // 32 + 8 pad (halves); 80B row stride -> ldmatrix conflict-free

template<int MODE>
__global__ __launch_bounds__(256) void hgemm_nt(
    const __half* __restrict__ A, const __half* __restrict__ W,
    const float* __restrict__ R, void* __restrict__ Cv, int N, int K)
{
    __shared__ __half As[2][128][BKP];
    __shared__ __half Bs[2][128][BKP];

    int t = threadIdx.x;
    int warp = t >> 5, lane = t & 31;
    int wm = warp & 1, wn = warp >> 1;
    int lr = lane >> 2, lq = lane & 3;
    int rA = lane & 15, cSel = lane >> 4;    // ldmatrix lane addressing
    int m0 = blockIdx.y * 128, n0 = blockIdx.x * 128;

    int ldr = t >> 1, ldh = (t & 1) * 16;
    const __half* Ag = A + (size_t)(m0 + ldr) * K + ldh;
    const __half* Bg = W + (size_t)(n0 + ldr) * K + ldh;

    float c[4][4][4];
    #pragma unroll
    for (int mt = 0; mt < 4; mt++)
        #pragma unroll
        for (int nt = 0; nt < 4; nt++)
            #pragma unroll
            for (int i = 0; i < 4; i++) c[mt][nt][i] = 0.f;

    // preload tile 0
    {
        uint4 a0 = *(const uint4*)Ag, a1 = *(const uint4*)(Ag + 8);
        uint4 b0 = *(const uint4*)Bg, b1 = *(const uint4*)(Bg + 8);
        *(uint4*)&As[0][ldr][ldh]     = a0;
        *(uint4*)&As[0][ldr][ldh + 8] = a1;
        *(uint4*)&Bs[0][ldr][ldh]     = b0;
        *(uint4*)&Bs[0][ldr][ldh + 8] = b1;
    }
    __syncthreads();

    int nk = K >> 5;
    for (int kt = 0; kt < nk; kt++) {
        int buf = kt & 1;
        uint4 pa0, pa1, pb0, pb1;
        bool pre = (kt + 1 < nk);
        if (pre) {
            const __half* ap = Ag + (kt + 1) * 32;
            const __half* bp = Bg + (kt + 1) * 32;
            pa0 = *(const uint4*)ap; pa1 = *(const uint4*)(ap + 8);
            pb0 = *(const uint4*)bp; pb1 = *(const uint4*)(bp + 8);
        }

        #pragma unroll
        for (int k0 = 0; k0 < 32; k0 += 16) {
            uint32_t a[4][4], bb[2][4];
            #pragma unroll
            for (int mt = 0; mt < 4; mt++) {
                uint32_t addr = smem_u32(&As[buf][wm * 64 + mt * 16 + rA][k0 + cSel * 8]);
                LDSM_X4(a[mt][0], a[mt][1], a[mt][2], a[mt][3], addr);
            }
            #pragma unroll
            for (int np = 0; np < 2; np++) {
                uint32_t addr = smem_u32(&Bs[buf][wn * 32 + np * 16 + rA][k0 + cSel * 8]);
                LDSM_X4(bb[np][0], bb[np][1], bb[np][2], bb[np][3], addr);
            }
            #pragma unroll
            for (int mt = 0; mt < 4; mt++)
                #pragma unroll
                for (int nt = 0; nt < 4; nt++) {
                    int np = nt >> 1, od = nt & 1;
                    mma_f16(c[mt][nt], a[mt], bb[np][od], bb[np][od + 2]);
                }
        }

        if (pre) {
            int nb = buf ^ 1;
            *(uint4*)&As[nb][ldr][ldh]     = pa0;
            *(uint4*)&As[nb][ldr][ldh + 8] = pa1;
            *(uint4*)&Bs[nb][ldr][ldh]     = pb0;
            *(uint4*)&Bs[nb][ldr][ldh + 8] = pb1;
            __syncthreads();
        }
    }

    #pragma unroll
    for (int mt = 0; mt < 4; mt++) {
        int row = m0 + wm * 64 + mt * 16 + lr;
        #pragma unroll
        for (int nt = 0; nt < 4; nt++) {
            int col = n0 + wn * 32 + nt * 8 + 2 * lq;
            if (MODE == 0) {
                __half* C = (__half*)Cv;
                *(__half2*)(C + (size_t)row * N + col)       = __floats2half2_rn(c[mt][nt][0], c[mt][nt][1]);
                *(__half2*)(C + (size_t)(row + 8) * N + col) = __floats2half2_rn(c[mt][nt][2], c[mt][nt][3]);
            } else {
                float* C = (float*)Cv;
                float2 r0 = *(const float2*)(R + (size_t)row * N + col);
                float2 r1 = *(const float2*)(R + (size_t)(row + 8) * N + col);
                *(float2*)(C + (size_t)row * N + col)       = make_float2(c[mt][nt][0] + r0.x, c[mt][nt][1] + r0.y);
                *(float2*)(C + (size_t)(row + 8) * N + col) = make_float2(c[mt][nt][2] + r1.x, c[mt][nt][3] + r1.y);
            }
        }
    }
}

// ---------------------------------------------------------------------------
// 3) gate
// ---------------------------------------------------------------------------
__global__ __launch_bounds__(512) void gate_kernel(
    const __half* __restrict__ xn, const __half* __restrict__ gw, float* __restrict__ sg)
{
    int row = blockIdx.x;
    int h = threadIdx.x >> 5;
    int lane = threadIdx.x & 31;
    const __half2* xr = (const __half2*)(xn + (size_t)row * DIM);
    const __half2* wr = (const __half2*)(gw + (size_t)h * DIM);
    float acc = 0.f;
    #pragma unroll
    for (int i = lane; i < DIM / 2; i += 32) {
        float2 a = __half22float2(xr[i]);
        float2 b = __half22float2(wr[i]);
        acc = fmaf(a.x, b.x, acc);
        acc = fmaf(a.y, b.y, acc);
    }
    #pragma unroll
    for (int o = 16; o > 0; o >>= 1) acc += __shfl_down_sync(0xffffffffu, acc, o);
    if (lane == 0) sg[row * NH + h] = 1.f / (1.f + __expf(-acc));
}

// ---------------------------------------------------------------------------
// 4) q/k per-head RMS norm in place
// ---------------------------------------------------------------------------
__global__ __launch_bounds__(256) void qknorm_kernel(
    __half* __restrict__ qkv, const float* __restrict__ qw, const float* __restrict__ kw)
{
    int w = blockIdx.x * 8 + (threadIdx.x >> 5);
    int lane = threadIdx.x & 31;
    int bs = w >> 5;
    int rem = w & 31;
    int sel = rem >> 4;
    int h = rem & 15;
    __half2* p = (__half2*)(qkv + (size_t)bs * 3 * DIM + (size_t)sel * DIM + h * HD);
    float2 v = __half22float2(p[lane]);
    float ss = v.x * v.x + v.y * v.y;
    #pragma unroll
    for (int o = 16; o > 0; o >>= 1) ss += __shfl_xor_sync(0xffffffffu, ss, o);
    float scale = rsqrtf(ss * (1.0f / HD) + EPSV);
    const float* nw = sel ? kw : qw;
    p[lane] = __floats2half2_rn(v.x * scale * nw[2 * lane], v.y * scale * nw[2 * lane + 1]);
}

// ---------------------------------------------------------------------------
// 5) attention: 128 q-rows/block (8 warps), 64-key tiles, cp.async double
//    buffer, ldmatrix frags, exp2-domain softmax, gate fused.
// ---------------------------------------------------------------------------
#define KVP 72   // 64 + 8 pad halves; 144B stride, ldmatrix conflict-free

__global__ __launch_bounds__(256) void attn_f16(
    const __half* __restrict__ qkv, const float* __restrict__ sg, __half* __restrict__ att)
{
    __shared__ __half Ks[2][64][KVP];
    __shared__ __half Vs[2][64][KVP];

    int qb = blockIdx.x, h = blockIdx.y, b = blockIdx.z;
    int t = threadIdx.x, warp = t >> 5, lane = t & 31;
    int lr = lane >> 2, lq = lane & 3;
    int rA = lane & 15, cSel = lane >> 4;
    // trans-ldmatrix lane addressing
    int g8 = lane >> 3, w8 = lane & 7;
    int tRow = (g8 & 1) * 8 + w8, tCol = (g8 >> 1) * 8;

    // Q fragments pre-scaled by 0.125*log2(e) (exp2 domain)
    uint32_t aQ[4][4];
    {
        int r0 = qb * 128 + warp * 16 + lr;
        const __half* Qp  = qkv + ((size_t)(b * SQ) + r0) * (3 * DIM) + h * HD;
        const __half* Qp8 = Qp + 8 * (3 * DIM);
        __half2 s8 = __floats2half2_rn(0.1803368801f, 0.1803368801f);
        #pragma unroll
        for (int dt = 0; dt < 4; dt++) {
            aQ[dt][0] = h2u(__hmul2(*(const __half2*)(Qp  + dt * 16 + 2 * lq), s8));
            aQ[dt][1] = h2u(__hmul2(*(const __half2*)(Qp8 + dt * 16 + 2 * lq), s8));
            aQ[dt][2] = h2u(__hmul2(*(const __half2*)(Qp  + dt * 16 + 8 + 2 * lq), s8));
            aQ[dt][3] = h2u(__hmul2(*(const __half2*)(Qp8 + dt * 16 + 8 + 2 * lq), s8));
        }
    }

    float o[8][4];
    #pragma unroll
    for (int nt = 0; nt < 8; nt++)
        #pragma unroll
        for (int i = 0; i < 4; i++) o[nt][i] = 0.f;
    float m0 = -1e30f, m1 = -1e30f, l0 = 0.f, l1 = 0.f;

    // loader: 256 threads -> key = t&63, d-seg = (t>>6)*16
    int lkey = t & 63, lseg = (t >> 6) * 16;
    const __half* Kg = qkv + ((size_t)(b * SQ) + lkey) * (3 * DIM) + DIM + h * HD + lseg;
    const __half* Vg = Kg + DIM;

    // prologue: tile 0 -> buf 0
    {
        uint32_t ks = smem_u32(&Ks[0][lkey][lseg]);
        uint32_t vs = smem_u32(&Vs[0][lkey][lseg]);
        CP16(ks, Kg); CP16(ks + 16, Kg + 8);
        CP16(vs, Vg); CP16(vs + 16, Vg + 8);
        CP_COMMIT();
    }

    int ntiles = SQ / 64;
    for (int it = 0; it < ntiles; it++) {
        int buf = it & 1;
        CP_WAIT0();
        __syncthreads();

        if (it + 1 < ntiles) {
            int nb = buf ^ 1;
            const __half* kg = Kg + (size_t)(it + 1) * 64 * (3 * DIM);
            const __half* vg = Vg + (size_t)(it + 1) * 64 * (3 * DIM);
            uint32_t ks = smem_u32(&Ks[nb][lkey][lseg]);
            uint32_t vs = smem_u32(&Vs[nb][lkey][lseg]);
            CP16(ks, kg); CP16(ks + 16, kg + 8);
            CP16(vs, vg); CP16(vs + 16, vg + 8);
            CP_COMMIT();
        }

        // --- S = Q K^T (16 x 64 per warp), exp2 domain ---
        float sc[8][4];
        #pragma unroll
        for (int nt = 0; nt < 8; nt++)
            #pragma unroll
            for (int i = 0; i < 4; i++) sc[nt][i] = 0.f;

        #pragma unroll
        for (int dt = 0; dt < 4; dt++) {
            #pragma unroll
            for (int kb = 0; kb < 4; kb++) {
                uint32_t r0, r1, r2, r3;
                uint32_t addr = smem_u32(&Ks[buf][kb * 16 + rA][dt * 16 + cSel * 8]);
                LDSM_X4(r0, r1, r2, r3, addr);
                mma_f16(sc[2 * kb],     aQ[dt], r0, r2);
                mma_f16(sc[2 * kb + 1], aQ[dt], r1, r3);
            }
        }

        // --- online softmax (rows lr, lr+8) ---
        float rm0 = sc[0][0], rm1 = sc[0][2];
        #pragma unroll
        for (int nt = 0; nt < 8; nt++) {
            rm0 = fmaxf(rm0, fmaxf(sc[nt][0], sc[nt][1]));
            rm1 = fmaxf(rm1, fmaxf(sc[nt][2], sc[nt][3]));
        }
        rm0 = fmaxf(rm0, __shfl_xor_sync(0xffffffffu, rm0, 1));
        rm0 = fmaxf(rm0, __shfl_xor_sync(0xffffffffu, rm0, 2));
        rm1 = fmaxf(rm1, __shfl_xor_sync(0xffffffffu, rm1, 1));
        rm1 = fmaxf(rm1, __shfl_xor_sync(0xffffffffu, rm1, 2));
        float mn0 = fmaxf(m0, rm0), mn1 = fmaxf(m1, rm1);
        float co0 = exp2f(m0 - mn0), co1 = exp2f(m1 - mn1);
        float sum0 = 0.f, sum1 = 0.f;
        #pragma unroll
        for (int nt = 0; nt < 8; nt++) {
            sc[nt][0] = exp2f(sc[nt][0] - mn0);
            sc[nt][1] = exp2f(sc[nt][1] - mn0);
            sc[nt][2] = exp2f(sc[nt][2] - mn1);
            sc[nt][3] = exp2f(sc[nt][3] - mn1);
            sum0 += sc[nt][0] + sc[nt][1];
            sum1 += sc[nt][2] + sc[nt][3];
        }
        sum0 += __shfl_xor_sync(0xffffffffu, sum0, 1);
        sum0 += __shfl_xor_sync(0xffffffffu, sum0, 2);
        sum1 += __shfl_xor_sync(0xffffffffu, sum1, 1);
        sum1 += __shfl_xor_sync(0xffffffffu, sum1, 2);
        l0 = l0 * co0 + sum0;
        l1 = l1 * co1 + sum1;
        #pragma unroll
        for (int nt = 0; nt < 8; nt++) {
            o[nt][0] *= co0; o[nt][1] *= co0;
            o[nt][2] *= co1; o[nt][3] *= co1;
        }
        m0 = mn0; m1 = mn1;

        // --- PV: P in registers, V b-frags via ldmatrix.trans ---
        #pragma unroll
        for (int kt = 0; kt < 4; kt++) {
            uint32_t aP[4];
            aP[0] = h2u(__floats2half2_rn(sc[2 * kt][0],     sc[2 * kt][1]));
            aP[1] = h2u(__floats2half2_rn(sc[2 * kt][2],     sc[2 * kt][3]));
            aP[2] = h2u(__floats2half2_rn(sc[2 * kt + 1][0], sc[2 * kt + 1][1]));
            aP[3] = h2u(__floats2half2_rn(sc[2 * kt + 1][2], sc[2 * kt + 1][3]));
            #pragma unroll
            for (int dp = 0; dp < 4; dp++) {
                uint32_t r0, r1, r2, r3;
                uint32_t addr = smem_u32(&Vs[buf][kt * 16 + tRow][dp * 16 + tCol]);
                LDSM_X4T(r0, r1, r2, r3, addr);
                mma_f16(o[2 * dp],     aP, r0, r1);
                mma_f16(o[2 * dp + 1], aP, r2, r3);
            }
        }
    }

    // --- epilogue: normalize, gate, store fp16 [b,s,h,d] ---
    int r0 = qb * 128 + warp * 16 + lr;
    int r1 = r0 + 8;
    float g0 = sg[((size_t)(b * SQ) + r0) * NH + h];
    float g1 = sg[((size_t)(b * SQ) + r1) * NH + h];
    float f0 = g0 / l0, f1 = g1 / l1;
    __half* o0 = att + ((size_t)(b * SQ) + r0) * DIM + h * HD;
    __half* o1 = att + ((size_t)(b * SQ) + r1) * DIM + h * HD;
    #pragma unroll
    for (int nt = 0; nt < 8; nt++) {
        int col = nt * 8 + 2 * lq;
        *(__half2*)(o0 + col) = __floats2half2_rn(o[nt][0] * f0, o[nt][1] * f0);
        *(__half2*)(o1 + col) = __floats2half2_rn(o[nt][2] * f1, o[nt][3] * f1);
    }
}

// ---------------------------------------------------------------------------
// launch
// ---------------------------------------------------------------------------
extern "C" void kernel_launch(void* const* d_in, const int* in_sizes, int n_in,
                              void* d_out, int out_size)
{
    const float* x         = (const float*)d_in[0];
    const float* prenorm_w = (const float*)d_in[1];
    const float* qkv_w     = (const float*)d_in[2];
    const float* gate_w    = (const float*)d_in[3];
    const float* o_w       = (const float*)d_in[4];
    const float* q_norm_w  = (const float*)d_in[5];
    const float* k_norm_w  = (const float*)d_in[6];
    float* out = (float*)d_out;

    __half *p_xnh, *p_qkvh, *p_atth, *p_qkv_wh, *p_o_wh, *p_gate_wh;
    float *p_gate;
    cudaGetSymbolAddress((void**)&p_xnh,    g_xnh);
    cudaGetSymbolAddress((void**)&p_qkvh,   g_qkvh);
    cudaGetSymbolAddress((void**)&p_atth,   g_atth);
    cudaGetSymbolAddress((void**)&p_gate,   g_gate);
    cudaGetSymbolAddress((void**)&p_qkv_wh, g_qkv_wh);
    cudaGetSymbolAddress((void**)&p_o_wh,   g_o_wh);
    cudaGetSymbolAddress((void**)&p_gate_wh,g_gate_wh);

    int wtot4 = (QKV_WN + O_WN + G_WN) / 4;
    convert_w<<<(wtot4 + 255) / 256, 256>>>(qkv_w, o_w, gate_w, p_qkv_wh, p_o_wh, p_gate_wh);

    prenorm_kernel<<<ROWS, 256>>>(x, prenorm_w, p_xnh);

    hgemm_nt<0><<<dim3(3 * DIM / 128, ROWS / 128), 256>>>(p_xnh, p_qkv_wh, nullptr, p_qkvh, 3 * DIM, DIM);

    gate_kernel<<<ROWS, 512>>>(p_xnh, p_gate_wh, p_gate);

    qknorm_kernel<<<ROWS * 32 / 8, 256>>>(p_qkvh, q_norm_w, k_norm_w);

    attn_f16<<<dim3(SQ / 128, NH, BATCH), 256>>>(p_qkvh, p_gate, p_atth);

    hgemm_nt<1><<<dim3(DIM / 128, ROWS / 128), 256>>>(p_atth, p_o_wh, x, out, DIM, DIM);
}

// round 5
// speedup vs baseline: 6.8348x; 1.0569x over previous
#include <cuda_runtime.h>
#include <cuda_fp16.h>
#include <math.h>
#include <stdint.h>

#define BATCH 2
#define SQ    2048
#define DIM   1024
#define NH    16
#define HD    64
#define ROWS  (BATCH * SQ)   // 4096
#define EPSV  1e-5f

#define NFULL 3200           // 3072 qkv + 16 gate + 112 zero pad

// ---------------------------------------------------------------------------
// Scratch (device globals)
// ---------------------------------------------------------------------------
__device__ __half g_xnh[ROWS * DIM];
__device__ __half g_qkvh[ROWS * 3 * DIM];
__device__ __half g_atth[ROWS * DIM];
__device__ float  g_gate[ROWS * NH];
__device__ __half g_wfull[NFULL * DIM];    // qkv_w + gate_w + zero pad
__device__ __half g_o_wh[DIM * DIM];

// ---------------------------------------------------------------------------
// PTX helpers
// ---------------------------------------------------------------------------
__device__ __forceinline__ void mma_f16(float* d, const uint32_t* a, uint32_t b0, uint32_t b1) {
    asm volatile(
        "mma.sync.aligned.m16n8k16.row.col.f32.f16.f16.f32 "
        "{%0,%1,%2,%3},{%4,%5,%6,%7},{%8,%9},{%0,%1,%2,%3};"
        : "+f"(d[0]), "+f"(d[1]), "+f"(d[2]), "+f"(d[3])
        : "r"(a[0]), "r"(a[1]), "r"(a[2]), "r"(a[3]), "r"(b0), "r"(b1));
}

__device__ __forceinline__ uint32_t h2u(__half2 v) { return *(uint32_t*)&v; }
__device__ __forceinline__ uint32_t smem_u32(const void* p) {
    return (uint32_t)__cvta_generic_to_shared(p);
}
__device__ __forceinline__ uint32_t ex2_h2(uint32_t x) {
    uint32_t r;
    asm("ex2.approx.f16x2 %0, %1;" : "=r"(r) : "r"(x));
    return r;
}

#define LDSM_X4(r0, r1, r2, r3, addr) \
    asm volatile("ldmatrix.sync.aligned.m8n8.x4.shared.b16 {%0,%1,%2,%3},[%4];" \
        : "=r"(r0), "=r"(r1), "=r"(r2), "=r"(r3) : "r"(addr))

#define LDSM_X4T(r0, r1, r2, r3, addr) \
    asm volatile("ldmatrix.sync.aligned.m8n8.x4.trans.shared.b16 {%0,%1,%2,%3},[%4];" \
        : "=r"(r0), "=r"(r1), "=r"(r2), "=r"(r3) : "r"(addr))

#define CP16(smem, gptr) \
    asm volatile("cp.async.cg.shared.global [%0], [%1], 16;" :: "r"(smem), "l"(gptr))
#define CP_COMMIT() asm volatile("cp.async.commit_group;")
#define CP_WAIT0()  asm volatile("cp.async.wait_group 0;")

// ---------------------------------------------------------------------------
// 0) weight conversion fp32 -> fp16, build fused [qkv; gate; 0] matrix
// ---------------------------------------------------------------------------
#define QKV_WN (3 * DIM * DIM)          // 3145728
#define G_WN   (NH * DIM)               // 16384
#define WF_N   (NFULL * DIM)            // 3276800
#define O_WN   (DIM * DIM)              // 1048576
#define CV_TOT ((WF_N + O_WN) / 4)

__global__ __launch_bounds__(256) void convert_w(
    const float* __restrict__ qkv_w, const float* __restrict__ gate_w,
    const float* __restrict__ o_w,
    __half* __restrict__ wfull, __half* __restrict__ o_wh)
{
    int i = (blockIdx.x * 256 + threadIdx.x) * 4;
    if (i >= WF_N + O_WN) return;
    const float* src;
    __half* dst;
    if (i < QKV_WN)              { src = qkv_w + i;                 dst = wfull + i; }
    else if (i < QKV_WN + G_WN)  { src = gate_w + (i - QKV_WN);     dst = wfull + i; }
    else if (i < WF_N)           { *(uint2*)(wfull + i) = make_uint2(0, 0); return; }
    else                         { src = o_w + (i - WF_N);          dst = o_wh + (i - WF_N); }
    float4 v = *(const float4*)src;
    *(__half2*)(dst)     = __floats2half2_rn(v.x, v.y);
    *(__half2*)(dst + 2) = __floats2half2_rn(v.z, v.w);
}

// ---------------------------------------------------------------------------
// 1) prenorm RMS -> fp16, single pass (values held in registers)
// ---------------------------------------------------------------------------
__global__ __launch_bounds__(256) void prenorm_kernel(
    const float* __restrict__ x, const float* __restrict__ w, __half* __restrict__ xn)
{
    int row = blockIdx.x, t = threadIdx.x;
    float4 v = *(const float4*)(x + (size_t)row * DIM + t * 4);
    float ss = v.x * v.x + v.y * v.y + v.z * v.z + v.w * v.w;
    #pragma unroll
    for (int o = 16; o > 0; o >>= 1) ss += __shfl_xor_sync(0xffffffffu, ss, o);
    __shared__ float red[8];
    if ((t & 31) == 0) red[t >> 5] = ss;
    __syncthreads();
    float tot = red[0] + red[1] + red[2] + red[3] + red[4] + red[5] + red[6] + red[7];
    float scale = rsqrtf(tot * (1.0f / DIM) + EPSV);
    float4 wv = *(const float4*)(w + t * 4);
    __half2 h0 = __floats2half2_rn(v.x * scale * wv.x, v.y * scale * wv.y);
    __half2 h1 = __floats2half2_rn(v.z * scale * wv.z, v.w * scale * wv.w);
    *(uint2*)(xn + (size_t)row * DIM + t * 4) = make_uint2(h2u(h0), h2u(h1));
}

// ---------------------------------------------------------------------------
// 2) fp16 NT GEMM, cp.async double-buffer, ldmatrix frags
//    128x128 tile, BK=32, 256 threads (8 warps 2x4), warp 64x32
//    MODE 1: fp32 C + fp32 residual R     (O projection)
//    MODE 2: fp16 qkv (stride 3072) + sigmoid gate cols [3072,3088)
// ---------------------------------------------------------------------------
#define BKP 40   // 80B row stride, ldmatrix conflict-free

template<int MODE>
__global__ __launch_bounds__(256) void hgemm_nt(
    const __half* __restrict__ A, const __half* __restrict__ W,
    const float* __restrict__ R, void* __restrict__ Cv,
    float* __restrict__ gate, int N, int K)
{
    __shared__ __half As[2][128][BKP];
    __shared__ __half Bs[2][128][BKP];

    int t = threadIdx.x;
    int warp = t >> 5, lane = t & 31;
    int wm = warp & 1, wn = warp >> 1;
    int lr = lane >> 2, lq = lane & 3;
    int rA = lane & 15, cSel = lane >> 4;
    int m0 = blockIdx.y * 128, n0 = blockIdx.x * 128;

    int ldr = t >> 1, ldh = (t & 1) * 16;
    const __half* Ag = A + (size_t)(m0 + ldr) * K + ldh;
    const __half* Bg = W + (size_t)(n0 + ldr) * K + ldh;

    float c[4][4][4];
    #pragma unroll
    for (int mt = 0; mt < 4; mt++)
        #pragma unroll
        for (int nt = 0; nt < 4; nt++)
            #pragma unroll
            for (int i = 0; i < 4; i++) c[mt][nt][i] = 0.f;

    // prologue: tile 0 -> buf 0
    {
        uint32_t as = smem_u32(&As[0][ldr][ldh]);
        uint32_t bs = smem_u32(&Bs[0][ldr][ldh]);
        CP16(as, Ag); CP16(as + 16, Ag + 8);
        CP16(bs, Bg); CP16(bs + 16, Bg + 8);
        CP_COMMIT();
    }

    int nk = K >> 5;
    for (int kt = 0; kt < nk; kt++) {
        int buf = kt & 1;
        CP_WAIT0();
        __syncthreads();

        if (kt + 1 < nk) {
            int nb = buf ^ 1;
            const __half* ap = Ag + (kt + 1) * 32;
            const __half* bp = Bg + (kt + 1) * 32;
            uint32_t as = smem_u32(&As[nb][ldr][ldh]);
            uint32_t bs = smem_u32(&Bs[nb][ldr][ldh]);
            CP16(as, ap); CP16(as + 16, ap + 8);
            CP16(bs, bp); CP16(bs + 16, bp + 8);
            CP_COMMIT();
        }

        #pragma unroll
        for (int k0 = 0; k0 < 32; k0 += 16) {
            uint32_t a[4][4], bb[2][4];
            #pragma unroll
            for (int mt = 0; mt < 4; mt++) {
                uint32_t addr = smem_u32(&As[buf][wm * 64 + mt * 16 + rA][k0 + cSel * 8]);
                LDSM_X4(a[mt][0], a[mt][1], a[mt][2], a[mt][3], addr);
            }
            #pragma unroll
            for (int np = 0; np < 2; np++) {
                uint32_t addr = smem_u32(&Bs[buf][wn * 32 + np * 16 + rA][k0 + cSel * 8]);
                LDSM_X4(bb[np][0], bb[np][1], bb[np][2], bb[np][3], addr);
            }
            #pragma unroll
            for (int mt = 0; mt < 4; mt++)
                #pragma unroll
                for (int nt = 0; nt < 4; nt++) {
                    int np = nt >> 1, od = nt & 1;
                    mma_f16(c[mt][nt], a[mt], bb[np][od], bb[np][od + 2]);
                }
        }
    }

    #pragma unroll
    for (int mt = 0; mt < 4; mt++) {
        int row = m0 + wm * 64 + mt * 16 + lr;
        #pragma unroll
        for (int nt = 0; nt < 4; nt++) {
            int col = n0 + wn * 32 + nt * 8 + 2 * lq;
            if (MODE == 1) {
                float* C = (float*)Cv;
                float2 r0 = *(const float2*)(R + (size_t)row * N + col);
                float2 r1 = *(const float2*)(R + (size_t)(row + 8) * N + col);
                *(float2*)(C + (size_t)row * N + col)       = make_float2(c[mt][nt][0] + r0.x, c[mt][nt][1] + r0.y);
                *(float2*)(C + (size_t)(row + 8) * N + col) = make_float2(c[mt][nt][2] + r1.x, c[mt][nt][3] + r1.y);
            } else {
                if (col < 3 * DIM) {
                    __half* C = (__half*)Cv;
                    *(__half2*)(C + (size_t)row * (3 * DIM) + col)       = __floats2half2_rn(c[mt][nt][0], c[mt][nt][1]);
                    *(__half2*)(C + (size_t)(row + 8) * (3 * DIM) + col) = __floats2half2_rn(c[mt][nt][2], c[mt][nt][3]);
                } else if (col < 3 * DIM + NH) {
                    int gc = col - 3 * DIM;
                    gate[(size_t)row * NH + gc]           = 1.f / (1.f + __expf(-c[mt][nt][0]));
                    gate[(size_t)row * NH + gc + 1]       = 1.f / (1.f + __expf(-c[mt][nt][1]));
                    gate[(size_t)(row + 8) * NH + gc]     = 1.f / (1.f + __expf(-c[mt][nt][2]));
                    gate[(size_t)(row + 8) * NH + gc + 1] = 1.f / (1.f + __expf(-c[mt][nt][3]));
                }
            }
        }
    }
}

// ---------------------------------------------------------------------------
// 4) q/k per-head RMS norm in place: 16 lanes per 64-elem group, 4 halves/thread
// ---------------------------------------------------------------------------
__global__ __launch_bounds__(256) void qknorm_kernel(
    __half* __restrict__ qkv, const float* __restrict__ qw, const float* __restrict__ kw)
{
    int wrp = blockIdx.x * 8 + (threadIdx.x >> 5);
    int lane = threadIdx.x & 31;
    int g = wrp * 2 + (lane >> 4);       // group index, 0 .. ROWS*32-1
    int l16 = lane & 15;
    int bs = g >> 5;
    int rem = g & 31;
    int sel = rem >> 4;
    int h = rem & 15;
    __half* p = qkv + (size_t)bs * 3 * DIM + (size_t)sel * DIM + h * HD + l16 * 4;
    uint2 raw = *(const uint2*)p;
    float2 v0 = __half22float2(*(__half2*)&raw.x);
    float2 v1 = __half22float2(*(__half2*)&raw.y);
    float ss = v0.x * v0.x + v0.y * v0.y + v1.x * v1.x + v1.y * v1.y;
    #pragma unroll
    for (int o = 8; o > 0; o >>= 1) ss += __shfl_xor_sync(0xffffffffu, ss, o);
    float scale = rsqrtf(ss * (1.0f / HD) + EPSV);
    const float* nw = (sel ? kw : qw) + l16 * 4;
    __half2 h0 = __floats2half2_rn(v0.x * scale * nw[0], v0.y * scale * nw[1]);
    __half2 h1 = __floats2half2_rn(v1.x * scale * nw[2], v1.y * scale * nw[3]);
    *(uint2*)p = make_uint2(h2u(h0), h2u(h1));
}

// ---------------------------------------------------------------------------
// 5) attention: 128 q-rows/block (8 warps), 64-key tiles, cp.async double
//    buffer, ldmatrix frags, f16x2 ex2 softmax, l via ones-column mma.
// ---------------------------------------------------------------------------
#define KVP 72   // 144B stride, ldmatrix conflict-free

__global__ __launch_bounds__(256) void attn_f16(
    const __half* __restrict__ qkv, const float* __restrict__ sg, __half* __restrict__ att)
{
    __shared__ __half Ks[2][64][KVP];
    __shared__ __half Vs[2][64][KVP];

    int qb = blockIdx.x, h = blockIdx.y, b = blockIdx.z;
    int t = threadIdx.x, warp = t >> 5, lane = t & 31;
    int lr = lane >> 2, lq = lane & 3;
    int rA = lane & 15, cSel = lane >> 4;
    int g8 = lane >> 3, w8 = lane & 7;
    int tRow = (g8 & 1) * 8 + w8, tCol = (g8 >> 1) * 8;

    // ones B-fragment for row-sum mma (col 0 of an 8-wide block = 1)
    uint32_t bOnes = (lane < 4) ? 0x3C003C00u : 0u;

    // Q frags pre-scaled by 0.125*log2(e)
    uint32_t aQ[4][4];
    {
        int r0 = qb * 128 + warp * 16 + lr;
        const __half* Qp  = qkv + ((size_t)(b * SQ) + r0) * (3 * DIM) + h * HD;
        const __half* Qp8 = Qp + 8 * (3 * DIM);
        __half2 s8 = __floats2half2_rn(0.1803368801f, 0.1803368801f);
        #pragma unroll
        for (int dt = 0; dt < 4; dt++) {
            aQ[dt][0] = h2u(__hmul2(*(const __half2*)(Qp  + dt * 16 + 2 * lq), s8));
            aQ[dt][1] = h2u(__hmul2(*(const __half2*)(Qp8 + dt * 16 + 2 * lq), s8));
            aQ[dt][2] = h2u(__hmul2(*(const __half2*)(Qp  + dt * 16 + 8 + 2 * lq), s8));
            aQ[dt][3] = h2u(__hmul2(*(const __half2*)(Qp8 + dt * 16 + 8 + 2 * lq), s8));
        }
    }

    float o[8][4], lacc[4];
    #pragma unroll
    for (int nt = 0; nt < 8; nt++)
        #pragma unroll
        for (int i = 0; i < 4; i++) o[nt][i] = 0.f;
    #pragma unroll
    for (int i = 0; i < 4; i++) lacc[i] = 0.f;
    float m0 = -1e30f, m1 = -1e30f;

    int lkey = t & 63, lseg = (t >> 6) * 16;
    const __half* Kg = qkv + ((size_t)(b * SQ) + lkey) * (3 * DIM) + DIM + h * HD + lseg;
    const __half* Vg = Kg + DIM;

    {
        uint32_t ks = smem_u32(&Ks[0][lkey][lseg]);
        uint32_t vs = smem_u32(&Vs[0][lkey][lseg]);
        CP16(ks, Kg); CP16(ks + 16, Kg + 8);
        CP16(vs, Vg); CP16(vs + 16, Vg + 8);
        CP_COMMIT();
    }

    int ntiles = SQ / 64;
    for (int it = 0; it < ntiles; it++) {
        int buf = it & 1;
        CP_WAIT0();
        __syncthreads();

        if (it + 1 < ntiles) {
            int nb = buf ^ 1;
            const __half* kg = Kg + (size_t)(it + 1) * 64 * (3 * DIM);
            const __half* vg = Vg + (size_t)(it + 1) * 64 * (3 * DIM);
            uint32_t ks = smem_u32(&Ks[nb][lkey][lseg]);
            uint32_t vs = smem_u32(&Vs[nb][lkey][lseg]);
            CP16(ks, kg); CP16(ks + 16, kg + 8);
            CP16(vs, vg); CP16(vs + 16, vg + 8);
            CP_COMMIT();
        }

        // --- S = Q K^T (16 x 64 per warp), exp2 domain ---
        float sc[8][4];
        #pragma unroll
        for (int nt = 0; nt < 8; nt++)
            #pragma unroll
            for (int i = 0; i < 4; i++) sc[nt][i] = 0.f;

        #pragma unroll
        for (int dt = 0; dt < 4; dt++) {
            #pragma unroll
            for (int kb = 0; kb < 4; kb++) {
                uint32_t r0, r1, r2, r3;
                uint32_t addr = smem_u32(&Ks[buf][kb * 16 + rA][dt * 16 + cSel * 8]);
                LDSM_X4(r0, r1, r2, r3, addr);
                mma_f16(sc[2 * kb],     aQ[dt], r0, r2);
                mma_f16(sc[2 * kb + 1], aQ[dt], r1, r3);
            }
        }

        // --- online softmax (rows lr, lr+8): max + f16x2 exp ---
        float rm0 = sc[0][0], rm1 = sc[0][2];
        #pragma unroll
        for (int nt = 0; nt < 8; nt++) {
            rm0 = fmaxf(rm0, fmaxf(sc[nt][0], sc[nt][1]));
            rm1 = fmaxf(rm1, fmaxf(sc[nt][2], sc[nt][3]));
        }
        rm0 = fmaxf(rm0, __shfl_xor_sync(0xffffffffu, rm0, 1));
        rm0 = fmaxf(rm0, __shfl_xor_sync(0xffffffffu, rm0, 2));
        rm1 = fmaxf(rm1, __shfl_xor_sync(0xffffffffu, rm1, 1));
        rm1 = fmaxf(rm1, __shfl_xor_sync(0xffffffffu, rm1, 2));
        float mn0 = fmaxf(m0, rm0), mn1 = fmaxf(m1, rm1);
        float co0 = exp2f(m0 - mn0), co1 = exp2f(m1 - mn1);
        m0 = mn0; m1 = mn1;

        __half2 mh0 = __floats2half2_rn(mn0, mn0);
        __half2 mh1 = __floats2half2_rn(mn1, mn1);
        uint32_t pl[8], ph[8];
        #pragma unroll
        for (int nt = 0; nt < 8; nt++) {
            pl[nt] = ex2_h2(h2u(__hsub2(__floats2half2_rn(sc[nt][0], sc[nt][1]), mh0)));
            ph[nt] = ex2_h2(h2u(__hsub2(__floats2half2_rn(sc[nt][2], sc[nt][3]), mh1)));
        }

        #pragma unroll
        for (int nt = 0; nt < 8; nt++) {
            o[nt][0] *= co0; o[nt][1] *= co0;
            o[nt][2] *= co1; o[nt][3] *= co1;
        }
        lacc[0] *= co0; lacc[1] *= co0; lacc[2] *= co1; lacc[3] *= co1;

        // --- PV + row-sum mma ---
        #pragma unroll
        for (int kt = 0; kt < 4; kt++) {
            uint32_t aP[4];
            aP[0] = pl[2 * kt];     aP[1] = ph[2 * kt];
            aP[2] = pl[2 * kt + 1]; aP[3] = ph[2 * kt + 1];
            mma_f16(lacc, aP, bOnes, bOnes);
            #pragma unroll
            for (int dp = 0; dp < 4; dp++) {
                uint32_t r0, r1, r2, r3;
                uint32_t addr = smem_u32(&Vs[buf][kt * 16 + tRow][dp * 16 + tCol]);
                LDSM_X4T(r0, r1, r2, r3, addr);
                mma_f16(o[2 * dp],     aP, r0, r1);
                mma_f16(o[2 * dp + 1], aP, r2, r3);
            }
        }
    }

    // --- epilogue ---
    float l0 = __shfl_sync(0xffffffffu, lacc[0], lane & 28);
    float l1 = __shfl_sync(0xffffffffu, lacc[2], lane & 28);
    int r0 = qb * 128 + warp * 16 + lr;
    int r1 = r0 + 8;
    float g0 = sg[((size_t)(b * SQ) + r0) * NH + h];
    float g1 = sg[((size_t)(b * SQ) + r1) * NH + h];
    float f0 = g0 / l0, f1 = g1 / l1;
    __half* o0 = att + ((size_t)(b * SQ) + r0) * DIM + h * HD;
    __half* o1 = att + ((size_t)(b * SQ) + r1) * DIM + h * HD;
    #pragma unroll
    for (int nt = 0; nt < 8; nt++) {
        int col = nt * 8 + 2 * lq;
        *(__half2*)(o0 + col) = __floats2half2_rn(o[nt][0] * f0, o[nt][1] * f0);
        *(__half2*)(o1 + col) = __floats2half2_rn(o[nt][2] * f1, o[nt][3] * f1);
    }
}

// ---------------------------------------------------------------------------
// launch
// ---------------------------------------------------------------------------
extern "C" void kernel_launch(void* const* d_in, const int* in_sizes, int n_in,
                              void* d_out, int out_size)
{
    const float* x         = (const float*)d_in[0];
    const float* prenorm_w = (const float*)d_in[1];
    const float* qkv_w     = (const float*)d_in[2];
    const float* gate_w    = (const float*)d_in[3];
    const float* o_w       = (const float*)d_in[4];
    const float* q_norm_w  = (const float*)d_in[5];
    const float* k_norm_w  = (const float*)d_in[6];
    float* out = (float*)d_out;

    __half *p_xnh, *p_qkvh, *p_atth, *p_wfull, *p_o_wh;
    float *p_gate;
    cudaGetSymbolAddress((void**)&p_xnh,   g_xnh);
    cudaGetSymbolAddress((void**)&p_qkvh,  g_qkvh);
    cudaGetSymbolAddress((void**)&p_atth,  g_atth);
    cudaGetSymbolAddress((void**)&p_gate,  g_gate);
    cudaGetSymbolAddress((void**)&p_wfull, g_wfull);
    cudaGetSymbolAddress((void**)&p_o_wh,  g_o_wh);

    convert_w<<<(CV_TOT + 255) / 256, 256>>>(qkv_w, gate_w, o_w, p_wfull, p_o_wh);

    prenorm_kernel<<<ROWS, 256>>>(x, prenorm_w, p_xnh);

    // QKV + gate fused GEMM: [4096,1024] x [3200,1024]^T
    hgemm_nt<2><<<dim3(NFULL / 128, ROWS / 128), 256>>>(
        p_xnh, p_wfull, nullptr, p_qkvh, p_gate, NFULL, DIM);

    qknorm_kernel<<<ROWS * 32 / 16, 256>>>(p_qkvh, q_norm_w, k_norm_w);

    attn_f16<<<dim3(SQ / 128, NH, BATCH), 256>>>(p_qkvh, p_gate, p_atth);

    hgemm_nt<1><<<dim3(DIM / 128, ROWS / 128), 256>>>(
        p_atth, p_o_wh, x, out, nullptr, DIM, DIM);
}